// round 13
// baseline (speedup 1.0000x reference)
#include <cuda_runtime.h>
#include <cuda_bf16.h>
#include <cstdint>
#include <math.h>

// Problem constants
#define NTOK 8192
#define NROWS 262144
#define NTILES 2048
#define GRID_MAIN 148

// Scratch (static __device__ — no allocations allowed)
__device__ __nv_bfloat16 g_Btb[256*256];   // W_h top, transposed [n][k], bf16
__device__ __nv_bfloat16 g_Wfb[256*256];   // (W_ego @ W_h_bot) transposed [j][e], bf16
__device__ float g_fbpart[8*256];          // partial b_ego @ W_h_bot
__device__ float g_ego[NTOK*256];          // ego contribution (fp32)
__device__ float g_logits[NROWS*4];
__device__ int   g_det[8];                 // mask-is-byte partial flags

__device__ __forceinline__ float wsum(float v){
    #pragma unroll
    for (int o = 16; o; o >>= 1) v += __shfl_xor_sync(0xffffffffu, v, o);
    return v;
}
__device__ __forceinline__ float wmax(float v){
    #pragma unroll
    for (int o = 16; o; o >>= 1) v = fmaxf(v, __shfl_xor_sync(0xffffffffu, v, o));
    return v;
}
__device__ __forceinline__ float fast_tanh(float x){
    float y;
    asm("tanh.approx.f32 %0, %1;" : "=f"(y) : "f"(x));
    return y;
}
__device__ __forceinline__ float gelu_tanh(float x){
    float x3 = x * x * x;
    return 0.5f * x * (1.0f + fast_tanh(0.7978845608028654f * fmaf(0.044715f, x3, x)));
}
__device__ __forceinline__ uint32_t pack_bf2(float a, float b){
    __nv_bfloat162 h = __floats2bfloat162_rn(a, b);   // a -> .x (low)
    return *(uint32_t*)&h;
}

#define MMA_BF16(d, a, b0v, b1v) \
    asm("mma.sync.aligned.m16n8k16.row.col.f32.bf16.bf16.f32 " \
        "{%0,%1,%2,%3}, {%4,%5,%6,%7}, {%8,%9}, {%0,%1,%2,%3};" \
        : "+f"(d[0]), "+f"(d[1]), "+f"(d[2]), "+f"(d[3]) \
        : "r"(a[0]), "r"(a[1]), "r"(a[2]), "r"(a[3]), "r"(b0v), "r"(b1v))

#define LDSM_X4(r0, r1, r2, r3, addr) \
    asm volatile("ldmatrix.sync.aligned.m8n8.x4.shared.b16 {%0,%1,%2,%3}, [%4];" \
        : "=r"(r0), "=r"(r1), "=r"(r2), "=r"(r3) : "r"(addr))

#define CP_ASYNC16(dst, src) \
    asm volatile("cp.async.cg.shared.global [%0], [%1], 16;" \
        :: "r"(dst), "l"(src) : "memory")
#define CP_COMMIT() asm volatile("cp.async.commit_group;" ::: "memory")
#define CP_WAIT0()  asm volatile("cp.async.wait_group 0;" ::: "memory")

// ---------------------------------------------------------------------------
// k_prep: concurrent roles by blockIdx (unchanged, known good)
// ---------------------------------------------------------------------------
__global__ void __launch_bounds__(256) k_prep(const float* __restrict__ Wh,
                                              const float* __restrict__ We,
                                              const float* __restrict__ be,
                                              const void*  __restrict__ mask){
    int bid = blockIdx.x, tid = threadIdx.x;
    if (bid < 256){
        g_Btb[bid*256 + tid] = __float2bfloat16(Wh[tid*256 + bid]);
        __shared__ float s[256];
        s[tid] = We[bid*256 + tid];
        __syncthreads();
        float a0=0.f, a1=0.f, a2=0.f, a3=0.f;
        const float* Wb = Wh + 256*256 + tid;
        #pragma unroll 8
        for (int t = 0; t < 256; t += 4){
            a0 = fmaf(s[t],   Wb[(t  )*256], a0);
            a1 = fmaf(s[t+1], Wb[(t+1)*256], a1);
            a2 = fmaf(s[t+2], Wb[(t+2)*256], a2);
            a3 = fmaf(s[t+3], Wb[(t+3)*256], a3);
        }
        g_Wfb[tid*256 + bid] = __float2bfloat16((a0+a1) + (a2+a3));  // [j][e]
    } else if (bid < 264){
        int db = bid - 256;
        __shared__ int f;
        if (tid == 0) f = 0;
        __syncthreads();
        const uint4* m4 = (const uint4*)mask;
        unsigned loc = 0;
        #pragma unroll
        for (int q = 0; q < 8; q++){
            uint4 v = m4[db*2048 + q*256 + tid];
            loc |= (v.x | v.y | v.z | v.w) & 0xFFFFFF00u;
        }
        if (loc) atomicOr(&f, 1);
        __syncthreads();
        if (tid == 0) g_det[db] = f;
    } else {
        int db = bid - 264;
        __shared__ float s[32];
        if (tid < 32) s[tid] = be[db*32 + tid];
        __syncthreads();
        float acc = 0.f;
        const float* Wb = Wh + (256 + db*32)*256 + tid;
        #pragma unroll
        for (int t = 0; t < 32; t++)
            acc = fmaf(s[t], Wb[t*256], acc);
        g_fbpart[db*256 + tid] = acc;
    }
}

// Shared geometry (R6)
#define ASTB 264
#define BSTB 24
#define AS_BYTES (128*ASTB*2)        // 67584
#define BS_HALF  (256*BSTB)          // elems per k16 buffer (6144)
#define BS_BYTES (2*BS_HALF*2)       // 24576

// ---------------------------------------------------------------------------
// k_egomma: g_ego = ego_ctx @ Wf + biasc (R6 version, known good)
// ---------------------------------------------------------------------------
#define EGO_SMEM (AS_BYTES + BS_BYTES + 1024)
__global__ void __launch_bounds__(512, 1) k_egomma(const float* __restrict__ ego,
                                                   const float* __restrict__ bh){
    extern __shared__ char smraw[];
    __nv_bfloat16* As = (__nv_bfloat16*)smraw;
    __nv_bfloat16* Bs = (__nv_bfloat16*)(smraw + AS_BYTES);
    float* bias_sm    = (float*)(smraw + AS_BYTES + BS_BYTES);

    int tid = threadIdx.x, lane = tid & 31, wid = tid >> 5;
    int g = lane >> 2, tg = lane & 3;
    int wm = wid >> 2, wn = wid & 3;
    size_t rowbase = (size_t)blockIdx.x * 128;

    if (tid < 256){
        float b = bh[tid];
        #pragma unroll
        for (int q = 0; q < 8; q++) b += g_fbpart[q*256 + tid];
        bias_sm[tid] = b;
    }

    for (int rr = 0; rr < 8; rr++){
        int row = wid*8 + rr;
        const float4* src = (const float4*)(ego + (rowbase + row)*256);
        float4 v0 = src[lane*2], v1 = src[lane*2 + 1];
        uint4 pk;
        pk.x = pack_bf2(v0.x, v0.y);
        pk.y = pack_bf2(v0.z, v0.w);
        pk.z = pack_bf2(v1.x, v1.y);
        pk.w = pack_bf2(v1.z, v1.w);
        *(uint4*)(As + row*ASTB + lane*8) = pk;
    }

    float acc[2][8][4];
    #pragma unroll
    for (int mt = 0; mt < 2; mt++)
        #pragma unroll
        for (int nt = 0; nt < 8; nt++)
            #pragma unroll
            for (int e = 0; e < 4; e++) acc[mt][nt][e] = 0.f;

    int bn = tid & 255, bkh = tid >> 8;
    const uint4* Bg = (const uint4*)g_Wfb;
    uint4 pf = Bg[bn*32 + bkh];
    *(uint4*)(Bs + bn*BSTB + bkh*8) = pf;

    for (int ch = 0; ch < 16; ch++){
        __syncthreads();
        if (ch + 1 < 16) pf = Bg[bn*32 + (ch+1)*2 + bkh];
        const __nv_bfloat16* Bc = Bs + (ch & 1)*BS_HALF;

        uint32_t a[2][4];
        #pragma unroll
        for (int mt = 0; mt < 2; mt++){
            const __nv_bfloat16* Ar = As + (wm*32 + mt*16 + g)*ASTB + ch*16;
            a[mt][0] = *(const uint32_t*)(Ar + 2*tg);
            a[mt][1] = *(const uint32_t*)(Ar + 8*ASTB + 2*tg);
            a[mt][2] = *(const uint32_t*)(Ar + 2*tg + 8);
            a[mt][3] = *(const uint32_t*)(Ar + 8*ASTB + 2*tg + 8);
        }
        #pragma unroll
        for (int nt = 0; nt < 8; nt++){
            const __nv_bfloat16* Br = Bc + (wn*64 + nt*8 + g)*BSTB + 2*tg;
            uint32_t b0 = *(const uint32_t*)(Br);
            uint32_t b1 = *(const uint32_t*)(Br + 8);
            #pragma unroll
            for (int mt = 0; mt < 2; mt++)
                MMA_BF16(acc[mt][nt], a[mt], b0, b1);
        }
        if (ch + 1 < 16){
            __nv_bfloat16* Bn = Bs + ((ch+1) & 1)*BS_HALF;
            *(uint4*)(Bn + bn*BSTB + bkh*8) = pf;
        }
    }

    #pragma unroll
    for (int mt = 0; mt < 2; mt++)
        #pragma unroll
        for (int nt = 0; nt < 8; nt++){
            int c = wn*64 + nt*8 + 2*tg;
            float bx = bias_sm[c], by = bias_sm[c+1];
            #pragma unroll
            for (int hi = 0; hi < 2; hi++){
                int rrow = wm*32 + mt*16 + g + 8*hi;
                float2 v = make_float2(acc[mt][nt][hi*2] + bx,
                                       acc[mt][nt][hi*2+1] + by);
                *(float2*)&g_ego[(rowbase + rrow)*256 + c] = v;
            }
        }
}

__global__ void k_nop(){}

// ---------------------------------------------------------------------------
// k_main: PERSISTENT (grid=148), 1024 threads, R6 GEMM inner loop verbatim.
// Single 128KB smem stage for next tile's raw inv (cp.async issued at GEMM
// start, consumed by the next LN from smem -> inv DRAM latency hidden).
// SMEM: stage 131072 | As 67584 | B 24576 | Wl 4096 | Lsm 2048 = 229376
// ---------------------------------------------------------------------------
#define SM_STAGE 0
#define SM_AS    131072
#define SM_B     (SM_AS + AS_BYTES)                  // 198656
#define SM_WL    (SM_B + BS_BYTES)                   // 223232
#define SM_LS    (SM_WL + 4096)                      // 227328
#define MAIN_SMEM (SM_LS + 2048)                     // 229376

__global__ void __launch_bounds__(1024, 1) k_main(const float* __restrict__ inv,
                                                  const float* __restrict__ lns,
                                                  const float* __restrict__ lnb,
                                                  const float* __restrict__ Wl){
    extern __shared__ char smraw[];
    float*          Stg = (float*)(smraw + SM_STAGE);
    __nv_bfloat16*  As  = (__nv_bfloat16*)(smraw + SM_AS);
    __nv_bfloat16*  Bs  = (__nv_bfloat16*)(smraw + SM_B);
    float* Wls = (float*)(smraw + SM_WL);
    float* Lsm = (float*)(smraw + SM_LS);

    int tid = threadIdx.x, lane = tid & 31, wid = tid >> 5;
    int g = lane >> 2, tg = lane & 3;
    int wm = wid >> 3, wn = wid & 7;

    uint32_t smb = (uint32_t)__cvta_generic_to_shared(smraw);
    uint32_t stageAddr = smb + SM_STAGE + tid*16;

    // Prologue: stage inv tile for t0 = blockIdx.x
    {
        const char* src = (const char*)(inv + (size_t)blockIdx.x*128*256) + tid*16;
        #pragma unroll
        for (int q = 0; q < 8; q++)
            CP_ASYNC16(stageAddr + q*16384, src + q*16384);
        CP_COMMIT();
    }

    Wls[tid] = Wl[tid];
    if (tid < 512) Lsm[tid] = 0.f;

    // LN scale/bias for this lane's 8-element slice
    const float4* lns4 = (const float4*)lns;
    const float4* lnb4 = (const float4*)lnb;
    float4 sc0 = lns4[lane*2], sc1 = lns4[lane*2 + 1];
    float4 sb0 = lnb4[lane*2], sb1 = lnb4[lane*2 + 1];

    // ldmatrix lane addresses (R6)
    uint32_t aAddr = smb + SM_AS + ((wm*32 + (lane & 15))*ASTB + ((lane >> 4) << 3)) * 2;
    uint32_t bAddr = smb + SM_B + (((wn*32 + ((lane >> 1) & 8) + (lane & 7))*BSTB
                                  + (lane & 8))) * 2;

    const uint4* Bg = (const uint4*)g_Btb;
    int bn = tid >> 1, bhf = tid & 1;

    for (int t = blockIdx.x; t < NTILES; t += GRID_MAIN){
        size_t rowbase = (size_t)t * 128;

        CP_WAIT0();
        __syncthreads();            // stage holds inv_t; prev epilogue done

        // LN from smem stage: warp handles rows wid*4..+3
        #pragma unroll
        for (int rr = 0; rr < 4; rr++){
            int row = wid*4 + rr;
            const float4* src = (const float4*)Stg + row*64;
            float4 v0 = src[lane*2], v1 = src[lane*2 + 1];
            float s = v0.x+v0.y+v0.z+v0.w + v1.x+v1.y+v1.z+v1.w;
            float q = v0.x*v0.x+v0.y*v0.y+v0.z*v0.z+v0.w*v0.w
                    + v1.x*v1.x+v1.y*v1.y+v1.z*v1.z+v1.w*v1.w;
            s = wsum(s); q = wsum(q);
            float mean = s * (1.f/256.f);
            float var  = q * (1.f/256.f) - mean*mean;
            float rstd = rsqrtf(var + 1e-6f);
            uint4 pk;
            pk.x = pack_bf2((v0.x-mean)*rstd*sc0.x + sb0.x, (v0.y-mean)*rstd*sc0.y + sb0.y);
            pk.y = pack_bf2((v0.z-mean)*rstd*sc0.z + sb0.z, (v0.w-mean)*rstd*sc0.w + sb0.w);
            pk.z = pack_bf2((v1.x-mean)*rstd*sc1.x + sb1.x, (v1.y-mean)*rstd*sc1.y + sb1.y);
            pk.w = pack_bf2((v1.z-mean)*rstd*sc1.z + sb1.z, (v1.w-mean)*rstd*sc1.w + sb1.w);
            *(uint4*)(As + row*ASTB + lane*8) = pk;
        }
        __syncthreads();            // As ready; stage fully consumed

        // Issue next tile's inv into the (now free) stage — hides under GEMM
        if (t + GRID_MAIN < NTILES){
            const char* src = (const char*)(inv + (size_t)(t + GRID_MAIN)*128*256) + tid*16;
            #pragma unroll
            for (int q = 0; q < 8; q++)
                CP_ASYNC16(stageAddr + q*16384, src + q*16384);
            CP_COMMIT();
        }

        float acc[2][4][4];
        #pragma unroll
        for (int mt = 0; mt < 2; mt++)
            #pragma unroll
            for (int nt = 0; nt < 4; nt++)
                #pragma unroll
                for (int e = 0; e < 4; e++) acc[mt][nt][e] = 0.f;

        // B chunk 0 prefetch (R6 scheme)
        uint4 pf;
        if (tid < 512){
            pf = Bg[bn*32 + bhf];
            *(uint4*)(Bs + bn*BSTB + bhf*8) = pf;
        }

        for (int ch = 0; ch < 16; ch++){
            __syncthreads();
            if (tid < 512 && ch + 1 < 16) pf = Bg[bn*32 + (ch+1)*2 + bhf];
            uint32_t bufB = bAddr + (ch & 1) * (BS_HALF * 2);

            uint32_t a[2][4];
            LDSM_X4(a[0][0], a[0][1], a[0][2], a[0][3], aAddr + ch*32);
            LDSM_X4(a[1][0], a[1][1], a[1][2], a[1][3], aAddr + ch*32 + 16*ASTB*2);

            #pragma unroll
            for (int p = 0; p < 2; p++){
                uint32_t b[4];
                LDSM_X4(b[0], b[1], b[2], b[3], bufB + p*16*BSTB*2);
                #pragma unroll
                for (int q = 0; q < 2; q++){
                    int nt = p*2 + q;
                    #pragma unroll
                    for (int mt = 0; mt < 2; mt++)
                        MMA_BF16(acc[mt][nt], a[mt], b[2*q], b[2*q+1]);
                }
            }
            if (tid < 512 && ch + 1 < 16){
                __nv_bfloat16* Bn = Bs + ((ch+1) & 1)*BS_HALF;
                *(uint4*)(Bn + bn*BSTB + bhf*8) = pf;
            }
        }

        // Fragment-space epilogue (R6): warp wm owns token t*4 + wm
        size_t token = (size_t)t*4 + wm;
        const float* egorow = g_ego + token*256;

        float pl[4][4];
        #pragma unroll
        for (int i = 0; i < 4; i++)
            #pragma unroll
            for (int h = 0; h < 4; h++) pl[i][h] = 0.f;

        #pragma unroll
        for (int nt = 0; nt < 4; nt++){
            int c = wn*32 + nt*8 + 2*tg;
            float2 eg = *(const float2*)(egorow + c);
            float4 w0 = *(const float4*)(Wls + c*4);
            float4 w1 = *(const float4*)(Wls + (c+1)*4);
            #pragma unroll
            for (int mt = 0; mt < 2; mt++)
                #pragma unroll
                for (int hi = 0; hi < 2; hi++){
                    float gl0 = gelu_tanh(acc[mt][nt][hi*2]   + eg.x);
                    float gl1 = gelu_tanh(acc[mt][nt][hi*2+1] + eg.y);
                    int ri = mt*2 + hi;
                    pl[ri][0] = fmaf(gl0, w0.x, fmaf(gl1, w1.x, pl[ri][0]));
                    pl[ri][1] = fmaf(gl0, w0.y, fmaf(gl1, w1.y, pl[ri][1]));
                    pl[ri][2] = fmaf(gl0, w0.z, fmaf(gl1, w1.z, pl[ri][2]));
                    pl[ri][3] = fmaf(gl0, w0.w, fmaf(gl1, w1.w, pl[ri][3]));
                }
        }
        #pragma unroll
        for (int o = 1; o <= 2; o <<= 1)
            #pragma unroll
            for (int ri = 0; ri < 4; ri++)
                #pragma unroll
                for (int h = 0; h < 4; h++)
                    pl[ri][h] += __shfl_xor_sync(0xffffffffu, pl[ri][h], o);

        if (tg == 0){
            #pragma unroll
            for (int mt = 0; mt < 2; mt++)
                #pragma unroll
                for (int hi = 0; hi < 2; hi++){
                    int rrow = wm*32 + mt*16 + g + 8*hi;
                    #pragma unroll
                    for (int h = 0; h < 4; h++)
                        atomicAdd(&Lsm[rrow*4 + h], pl[mt*2+hi][h]);
                }
        }
        __syncthreads();
        if (tid < 512){
            g_logits[(rowbase + (tid >> 2))*4 + (tid & 3)] = Lsm[tid];
            Lsm[tid] = 0.f;     // re-zero for next tile (ordered by loop-top sync)
        }
    }
}

// ---------------------------------------------------------------------------
// k_final: masked softmax over K per head + alpha-weighted r/u reductions.
// ---------------------------------------------------------------------------
__global__ void __launch_bounds__(256) k_final(const float* __restrict__ r,
                                               const float* __restrict__ u,
                                               const void* __restrict__ mask,
                                               float* __restrict__ out){
    __shared__ int s_mb;
    int tid = threadIdx.x, lane = tid & 31, w = tid >> 5;
    if (tid == 0){
        int mb = 0;
        #pragma unroll
        for (int q = 0; q < 8; q++) mb |= g_det[q];
        s_mb = mb;
    }
    __syncthreads();
    int T = blockIdx.x * 8 + w;
    size_t row = (size_t)T * 32 + lane;

    float4 l4 = ((const float4*)g_logits)[row];
    float l[4] = {l4.x, l4.y, l4.z, l4.w};

    bool m;
    if (s_mb) m = ((const unsigned char*)mask)[row] != 0;
    else      m = ((const unsigned int*)mask)[row] != 0u;

    float a[4];
    #pragma unroll
    for (int h = 0; h < 4; h++){
        float v = m ? l[h] : -3.402823466e38f;
        float mx = wmax(v);
        float e  = m ? __expf(l[h] - mx) : 0.f;
        float s  = wsum(e);
        a[h] = (s > 0.f) ? (e / s) : 0.f;
    }

    float* alpha_out = out + 2 * (NTOK * 12);
    ((float4*)alpha_out)[row] = make_float4(a[0], a[1], a[2], a[3]);

    float rr[3], uu[3];
    #pragma unroll
    for (int d = 0; d < 3; d++){
        rr[d] = r[row*3 + d];
        uu[d] = u[row*3 + d];
    }

    float orv = 0.f, ouv = 0.f;
    #pragma unroll
    for (int p = 0; p < 12; p++){
        float v1 = a[p/3] * rr[p%3];
        float v2 = a[p/3] * uu[p%3];
        #pragma unroll
        for (int o = 16; o; o >>= 1){
            v1 += __shfl_xor_sync(0xffffffffu, v1, o);
            v2 += __shfl_xor_sync(0xffffffffu, v2, o);
        }
        if (lane == p) orv = v1;
        if (lane == p) ouv = v2;
    }
    if (lane < 12){
        out[(size_t)T*12 + lane]           = orv;   // v_r
        out[NTOK*12 + (size_t)T*12 + lane] = ouv;   // v_u
    }
}

// ---------------------------------------------------------------------------
extern "C" void kernel_launch(void* const* d_in, const int* in_sizes, int n_in,
                              void* d_out, int out_size){
    (void)in_sizes; (void)n_in; (void)out_size;
    const float* inv  = (const float*)d_in[0];   // inv_tok (B,N,K,D)
    const float* ego  = (const float*)d_in[1];   // ego_ctx (B,N,256)
    const float* r    = (const float*)d_in[2];   // (B,N,K,3)
    const float* u    = (const float*)d_in[3];   // (B,N,K,3)
    const void*  mask = d_in[4];                 // (B,N,K) bool/int
    const float* We   = (const float*)d_in[5];   // W_ego (256,256)
    const float* be   = (const float*)d_in[6];   // b_ego (256)
    const float* lns  = (const float*)d_in[7];   // ln_scale (256)
    const float* lnb  = (const float*)d_in[8];   // ln_bias (256)
    const float* Wh   = (const float*)d_in[9];   // W_h (512,256)
    const float* bh   = (const float*)d_in[10];  // b_h (256)
    const float* Wl   = (const float*)d_in[11];  // W_logit (256,4)
    // d_in[12] = b_logit: softmax-invariant, unused.

    cudaFuncSetAttribute(k_main,   cudaFuncAttributeMaxDynamicSharedMemorySize, MAIN_SMEM);
    cudaFuncSetAttribute(k_egomma, cudaFuncAttributeMaxDynamicSharedMemorySize, EGO_SMEM);

    k_prep<<<272, 256>>>(Wh, We, be, mask);
    k_egomma<<<NTOK/128, 512, EGO_SMEM>>>(ego, bh);
    k_nop<<<1, 32>>>();
    k_main<<<GRID_MAIN, 1024, MAIN_SMEM>>>(inv, lns, lnb, Wl);
    k_final<<<NTOK/8, 256>>>(r, u, mask, (float*)d_out);
}

// round 14
// speedup vs baseline: 1.2410x; 1.2410x over previous
#include <cuda_runtime.h>
#include <cuda_bf16.h>
#include <cstdint>
#include <math.h>

// Problem constants
#define NTOK 8192
#define NROWS 262144

// Scratch (static __device__ — no allocations allowed)
__device__ __nv_bfloat16 g_Btb[256*256];   // W_h top, transposed [n][k], bf16
__device__ __nv_bfloat16 g_Wfb[256*256];   // (W_ego @ W_h_bot) transposed [j][e], bf16
__device__ float g_fbpart[8*256];          // partial b_ego @ W_h_bot
__device__ float g_ego[NTOK*256];          // ego contribution (fp32)
__device__ float g_logits[NROWS*4];
__device__ int   g_det[8];                 // mask-is-byte partial flags

__device__ __forceinline__ float wsum(float v){
    #pragma unroll
    for (int o = 16; o; o >>= 1) v += __shfl_xor_sync(0xffffffffu, v, o);
    return v;
}
__device__ __forceinline__ float wmax(float v){
    #pragma unroll
    for (int o = 16; o; o >>= 1) v = fmaxf(v, __shfl_xor_sync(0xffffffffu, v, o));
    return v;
}
__device__ __forceinline__ float fast_tanh(float x){
    float y;
    asm("tanh.approx.f32 %0, %1;" : "=f"(y) : "f"(x));
    return y;
}
__device__ __forceinline__ float gelu_tanh(float x){
    float x3 = x * x * x;
    return 0.5f * x * (1.0f + fast_tanh(0.7978845608028654f * fmaf(0.044715f, x3, x)));
}
__device__ __forceinline__ uint32_t pack_bf2(float a, float b){
    __nv_bfloat162 h = __floats2bfloat162_rn(a, b);   // a -> .x (low)
    return *(uint32_t*)&h;
}

#define MMA_BF16(d, a, b0v, b1v) \
    asm("mma.sync.aligned.m16n8k16.row.col.f32.bf16.bf16.f32 " \
        "{%0,%1,%2,%3}, {%4,%5,%6,%7}, {%8,%9}, {%0,%1,%2,%3};" \
        : "+f"(d[0]), "+f"(d[1]), "+f"(d[2]), "+f"(d[3]) \
        : "r"(a[0]), "r"(a[1]), "r"(a[2]), "r"(a[3]), "r"(b0v), "r"(b1v))

#define LDSM_X4(r0, r1, r2, r3, addr) \
    asm volatile("ldmatrix.sync.aligned.m8n8.x4.shared.b16 {%0,%1,%2,%3}, [%4];" \
        : "=r"(r0), "=r"(r1), "=r"(r2), "=r"(r3) : "r"(addr))

// ---------------------------------------------------------------------------
// k_prep: concurrent roles by blockIdx:
//   0..255   : g_Btb column (bf16 transpose of W_h top) + g_Wfb column
//   256..263 : mask width detect -> g_det
//   264..271 : b_ego @ W_h_bot partials -> g_fbpart
// ---------------------------------------------------------------------------
__global__ void __launch_bounds__(256) k_prep(const float* __restrict__ Wh,
                                              const float* __restrict__ We,
                                              const float* __restrict__ be,
                                              const void*  __restrict__ mask){
    int bid = blockIdx.x, tid = threadIdx.x;
    if (bid < 256){
        g_Btb[bid*256 + tid] = __float2bfloat16(Wh[tid*256 + bid]);
        __shared__ float s[256];
        s[tid] = We[bid*256 + tid];
        __syncthreads();
        float a0=0.f, a1=0.f, a2=0.f, a3=0.f;
        const float* Wb = Wh + 256*256 + tid;
        #pragma unroll 8
        for (int t = 0; t < 256; t += 4){
            a0 = fmaf(s[t],   Wb[(t  )*256], a0);
            a1 = fmaf(s[t+1], Wb[(t+1)*256], a1);
            a2 = fmaf(s[t+2], Wb[(t+2)*256], a2);
            a3 = fmaf(s[t+3], Wb[(t+3)*256], a3);
        }
        g_Wfb[tid*256 + bid] = __float2bfloat16((a0+a1) + (a2+a3));  // [j][e]
    } else if (bid < 264){
        int db = bid - 256;
        __shared__ int f;
        if (tid == 0) f = 0;
        __syncthreads();
        const uint4* m4 = (const uint4*)mask;
        unsigned loc = 0;
        #pragma unroll
        for (int q = 0; q < 8; q++){
            uint4 v = m4[db*2048 + q*256 + tid];
            loc |= (v.x | v.y | v.z | v.w) & 0xFFFFFF00u;
        }
        if (loc) atomicOr(&f, 1);
        __syncthreads();
        if (tid == 0) g_det[db] = f;
    } else {
        int db = bid - 264;
        __shared__ float s[32];
        if (tid < 32) s[tid] = be[db*32 + tid];
        __syncthreads();
        float acc = 0.f;
        const float* Wb = Wh + (256 + db*32)*256 + tid;
        #pragma unroll
        for (int t = 0; t < 32; t++)
            acc = fmaf(s[t], Wb[t*256], acc);
        g_fbpart[db*256 + tid] = acc;
    }
}

// Shared geometry
#define ASTB 264
#define BSTB 24
#define AS_BYTES (128*ASTB*2)        // 67584
#define BS_HALF  (256*BSTB)          // elems per k16 buffer (6144)
#define BS_BYTES (2*BS_HALF*2)       // 24576

// ---------------------------------------------------------------------------
// k_egomma: g_ego = ego_ctx @ Wf + biasc (512 threads, 16 warps, m32n64)
// ---------------------------------------------------------------------------
#define EGO_SMEM (AS_BYTES + BS_BYTES + 1024)
__global__ void __launch_bounds__(512, 1) k_egomma(const float* __restrict__ ego,
                                                   const float* __restrict__ bh){
    extern __shared__ char smraw[];
    __nv_bfloat16* As = (__nv_bfloat16*)smraw;
    __nv_bfloat16* Bs = (__nv_bfloat16*)(smraw + AS_BYTES);
    float* bias_sm    = (float*)(smraw + AS_BYTES + BS_BYTES);

    int tid = threadIdx.x, lane = tid & 31, wid = tid >> 5;
    int g = lane >> 2, tg = lane & 3;
    int wm = wid >> 2, wn = wid & 3;
    size_t rowbase = (size_t)blockIdx.x * 128;

    if (tid < 256){
        float b = bh[tid];
        #pragma unroll
        for (int q = 0; q < 8; q++) b += g_fbpart[q*256 + tid];
        bias_sm[tid] = b;
    }

    for (int rr = 0; rr < 8; rr++){
        int row = wid*8 + rr;
        const float4* src = (const float4*)(ego + (rowbase + row)*256);
        float4 v0 = src[lane*2], v1 = src[lane*2 + 1];
        uint4 pk;
        pk.x = pack_bf2(v0.x, v0.y);
        pk.y = pack_bf2(v0.z, v0.w);
        pk.z = pack_bf2(v1.x, v1.y);
        pk.w = pack_bf2(v1.z, v1.w);
        *(uint4*)(As + row*ASTB + lane*8) = pk;
    }

    float acc[2][8][4];
    #pragma unroll
    for (int mt = 0; mt < 2; mt++)
        #pragma unroll
        for (int nt = 0; nt < 8; nt++)
            #pragma unroll
            for (int e = 0; e < 4; e++) acc[mt][nt][e] = 0.f;

    int bn = tid & 255, bkh = tid >> 8;
    const uint4* Bg = (const uint4*)g_Wfb;
    uint4 pf = Bg[bn*32 + bkh];
    *(uint4*)(Bs + bn*BSTB + bkh*8) = pf;

    for (int ch = 0; ch < 16; ch++){
        __syncthreads();
        if (ch + 1 < 16) pf = Bg[bn*32 + (ch+1)*2 + bkh];
        const __nv_bfloat16* Bc = Bs + (ch & 1)*BS_HALF;

        uint32_t a[2][4];
        #pragma unroll
        for (int mt = 0; mt < 2; mt++){
            const __nv_bfloat16* Ar = As + (wm*32 + mt*16 + g)*ASTB + ch*16;
            a[mt][0] = *(const uint32_t*)(Ar + 2*tg);
            a[mt][1] = *(const uint32_t*)(Ar + 8*ASTB + 2*tg);
            a[mt][2] = *(const uint32_t*)(Ar + 2*tg + 8);
            a[mt][3] = *(const uint32_t*)(Ar + 8*ASTB + 2*tg + 8);
        }
        #pragma unroll
        for (int nt = 0; nt < 8; nt++){
            const __nv_bfloat16* Br = Bc + (wn*64 + nt*8 + g)*BSTB + 2*tg;
            uint32_t b0 = *(const uint32_t*)(Br);
            uint32_t b1 = *(const uint32_t*)(Br + 8);
            #pragma unroll
            for (int mt = 0; mt < 2; mt++)
                MMA_BF16(acc[mt][nt], a[mt], b0, b1);
        }
        if (ch + 1 < 16){
            __nv_bfloat16* Bn = Bs + ((ch+1) & 1)*BS_HALF;
            *(uint4*)(Bn + bn*BSTB + bkh*8) = pf;
        }
    }

    #pragma unroll
    for (int mt = 0; mt < 2; mt++)
        #pragma unroll
        for (int nt = 0; nt < 8; nt++){
            int c = wn*64 + nt*8 + 2*tg;
            float bx = bias_sm[c], by = bias_sm[c+1];
            #pragma unroll
            for (int hi = 0; hi < 2; hi++){
                int rrow = wm*32 + mt*16 + g + 8*hi;
                float2 v = make_float2(acc[mt][nt][hi*2] + bx,
                                       acc[mt][nt][hi*2+1] + by);
                *(float2*)&g_ego[(rowbase + rrow)*256 + c] = v;
            }
        }
}

// ---------------------------------------------------------------------------
// k_main: R6 measured-optimal configuration. 1024 threads, 32 warps (4M x 8N),
// warp tile m32 x n32, ldmatrix.x4 for A and B fragments, k16 chunks with
// register-prefetch double-buffered B. Fragment-space epilogue
// (+ego, gelu, logits, quad reduce, smem atomics) -> g_logits.
// ---------------------------------------------------------------------------
#define MAIN_SMEM (AS_BYTES + BS_BYTES + 4096 + 2048)
__global__ void __launch_bounds__(1024, 1) k_main(const float* __restrict__ inv,
                                                  const float* __restrict__ lns,
                                                  const float* __restrict__ lnb,
                                                  const float* __restrict__ Wl){
    extern __shared__ char smraw[];
    __nv_bfloat16* As = (__nv_bfloat16*)smraw;
    __nv_bfloat16* Bs = (__nv_bfloat16*)(smraw + AS_BYTES);
    float* Wls        = (float*)(smraw + AS_BYTES + BS_BYTES);          // 1024 f
    float* Lsm        = (float*)(smraw + AS_BYTES + BS_BYTES + 4096);   // 512 f

    int tid = threadIdx.x, lane = tid & 31, wid = tid >> 5;
    int g = lane >> 2, tg = lane & 3;
    int wm = wid >> 3, wn = wid & 7;
    size_t rowbase = (size_t)blockIdx.x * 128;

    Wls[tid] = Wl[tid];
    if (tid < 512) Lsm[tid] = 0.f;

    // LN scale/bias for this lane's 8-element slice
    const float4* lns4 = (const float4*)lns;
    const float4* lnb4 = (const float4*)lnb;
    float4 sc0 = lns4[lane*2], sc1 = lns4[lane*2 + 1];
    float4 sb0 = lnb4[lane*2], sb1 = lnb4[lane*2 + 1];

    // LN pre-pass: warp handles rows wid*4..+3
    #pragma unroll
    for (int rr = 0; rr < 4; rr++){
        int row = wid*4 + rr;
        const float4* src = (const float4*)(inv + (rowbase + row)*256);
        float4 v0 = src[lane*2], v1 = src[lane*2 + 1];
        float s = v0.x+v0.y+v0.z+v0.w + v1.x+v1.y+v1.z+v1.w;
        float q = v0.x*v0.x+v0.y*v0.y+v0.z*v0.z+v0.w*v0.w
                + v1.x*v1.x+v1.y*v1.y+v1.z*v1.z+v1.w*v1.w;
        s = wsum(s); q = wsum(q);
        float mean = s * (1.f/256.f);
        float var  = q * (1.f/256.f) - mean*mean;
        float rstd = rsqrtf(var + 1e-6f);
        uint4 pk;
        pk.x = pack_bf2((v0.x-mean)*rstd*sc0.x + sb0.x, (v0.y-mean)*rstd*sc0.y + sb0.y);
        pk.y = pack_bf2((v0.z-mean)*rstd*sc0.z + sb0.z, (v0.w-mean)*rstd*sc0.w + sb0.w);
        pk.z = pack_bf2((v1.x-mean)*rstd*sc1.x + sb1.x, (v1.y-mean)*rstd*sc1.y + sb1.y);
        pk.w = pack_bf2((v1.z-mean)*rstd*sc1.z + sb1.z, (v1.w-mean)*rstd*sc1.w + sb1.w);
        *(uint4*)(As + row*ASTB + lane*8) = pk;
    }

    float acc[2][4][4];
    #pragma unroll
    for (int mt = 0; mt < 2; mt++)
        #pragma unroll
        for (int nt = 0; nt < 4; nt++)
            #pragma unroll
            for (int e = 0; e < 4; e++) acc[mt][nt][e] = 0.f;

    // ldmatrix lane addresses
    uint32_t As_u32 = (uint32_t)__cvta_generic_to_shared(As);
    uint32_t Bs_u32 = (uint32_t)__cvta_generic_to_shared(Bs);
    uint32_t aAddr = As_u32 + ((wm*32 + (lane & 15))*ASTB + ((lane >> 4) << 3)) * 2;
    uint32_t bAddr = Bs_u32 + (((wn*32 + ((lane >> 1) & 8) + (lane & 7))*BSTB
                               + (lane & 8))) * 2;

    // B gmem prefetch: tid<512; n = tid>>1, half = tid&1
    const uint4* Bg = (const uint4*)g_Btb;
    int bn = tid >> 1, bhf = tid & 1;
    uint4 pf;
    if (tid < 512){
        pf = Bg[bn*32 + bhf];
        *(uint4*)(Bs + bn*BSTB + bhf*8) = pf;
    }

    for (int ch = 0; ch < 16; ch++){
        __syncthreads();
        if (tid < 512 && ch + 1 < 16) pf = Bg[bn*32 + (ch+1)*2 + bhf];
        uint32_t bufB = bAddr + (ch & 1) * (BS_HALF * 2);

        uint32_t a[2][4];
        LDSM_X4(a[0][0], a[0][1], a[0][2], a[0][3], aAddr + ch*32);
        LDSM_X4(a[1][0], a[1][1], a[1][2], a[1][3], aAddr + ch*32 + 16*ASTB*2);

        #pragma unroll
        for (int p = 0; p < 2; p++){
            uint32_t b[4];
            LDSM_X4(b[0], b[1], b[2], b[3], bufB + p*16*BSTB*2);
            #pragma unroll
            for (int q = 0; q < 2; q++){
                int nt = p*2 + q;
                #pragma unroll
                for (int mt = 0; mt < 2; mt++)
                    MMA_BF16(acc[mt][nt], a[mt], b[2*q], b[2*q+1]);
            }
        }
        if (tid < 512 && ch + 1 < 16){
            __nv_bfloat16* Bn = Bs + ((ch+1) & 1)*BS_HALF;
            *(uint4*)(Bn + bn*BSTB + bhf*8) = pf;
        }
    }

    // Fragment-space epilogue: warp wm owns token blockIdx*4 + wm
    size_t token = (size_t)blockIdx.x*4 + wm;
    const float* egorow = g_ego + token*256;

    float pl[4][4];
    #pragma unroll
    for (int i = 0; i < 4; i++)
        #pragma unroll
        for (int h = 0; h < 4; h++) pl[i][h] = 0.f;

    #pragma unroll
    for (int nt = 0; nt < 4; nt++){
        int c = wn*32 + nt*8 + 2*tg;
        float2 eg = *(const float2*)(egorow + c);
        float4 w0 = *(const float4*)(Wls + c*4);
        float4 w1 = *(const float4*)(Wls + (c+1)*4);
        #pragma unroll
        for (int mt = 0; mt < 2; mt++)
            #pragma unroll
            for (int hi = 0; hi < 2; hi++){
                float gl0 = gelu_tanh(acc[mt][nt][hi*2]   + eg.x);
                float gl1 = gelu_tanh(acc[mt][nt][hi*2+1] + eg.y);
                int ri = mt*2 + hi;
                pl[ri][0] = fmaf(gl0, w0.x, fmaf(gl1, w1.x, pl[ri][0]));
                pl[ri][1] = fmaf(gl0, w0.y, fmaf(gl1, w1.y, pl[ri][1]));
                pl[ri][2] = fmaf(gl0, w0.z, fmaf(gl1, w1.z, pl[ri][2]));
                pl[ri][3] = fmaf(gl0, w0.w, fmaf(gl1, w1.w, pl[ri][3]));
            }
    }
    // reduce over the 4 lanes of each quad
    #pragma unroll
    for (int o = 1; o <= 2; o <<= 1)
        #pragma unroll
        for (int ri = 0; ri < 4; ri++)
            #pragma unroll
            for (int h = 0; h < 4; h++)
                pl[ri][h] += __shfl_xor_sync(0xffffffffu, pl[ri][h], o);

    if (tg == 0){
        #pragma unroll
        for (int mt = 0; mt < 2; mt++)
            #pragma unroll
            for (int hi = 0; hi < 2; hi++){
                int rrow = wm*32 + mt*16 + g + 8*hi;
                #pragma unroll
                for (int h = 0; h < 4; h++)
                    atomicAdd(&Lsm[rrow*4 + h], pl[mt*2+hi][h]);
            }
    }
    __syncthreads();
    if (tid < 512)
        g_logits[(rowbase + (tid >> 2))*4 + (tid & 3)] = Lsm[tid];
}

// ---------------------------------------------------------------------------
// k_final: masked softmax over K per head + alpha-weighted r/u reductions.
// ---------------------------------------------------------------------------
__global__ void __launch_bounds__(256) k_final(const float* __restrict__ r,
                                               const float* __restrict__ u,
                                               const void* __restrict__ mask,
                                               float* __restrict__ out){
    __shared__ int s_mb;
    int tid = threadIdx.x, lane = tid & 31, w = tid >> 5;
    if (tid == 0){
        int mb = 0;
        #pragma unroll
        for (int q = 0; q < 8; q++) mb |= g_det[q];
        s_mb = mb;
    }
    __syncthreads();
    int T = blockIdx.x * 8 + w;
    size_t row = (size_t)T * 32 + lane;

    float4 l4 = ((const float4*)g_logits)[row];
    float l[4] = {l4.x, l4.y, l4.z, l4.w};

    bool m;
    if (s_mb) m = ((const unsigned char*)mask)[row] != 0;
    else      m = ((const unsigned int*)mask)[row] != 0u;

    float a[4];
    #pragma unroll
    for (int h = 0; h < 4; h++){
        float v = m ? l[h] : -3.402823466e38f;
        float mx = wmax(v);
        float e  = m ? __expf(l[h] - mx) : 0.f;
        float s  = wsum(e);
        a[h] = (s > 0.f) ? (e / s) : 0.f;
    }

    float* alpha_out = out + 2 * (NTOK * 12);
    ((float4*)alpha_out)[row] = make_float4(a[0], a[1], a[2], a[3]);

    float rr[3], uu[3];
    #pragma unroll
    for (int d = 0; d < 3; d++){
        rr[d] = r[row*3 + d];
        uu[d] = u[row*3 + d];
    }

    float orv = 0.f, ouv = 0.f;
    #pragma unroll
    for (int p = 0; p < 12; p++){
        float v1 = a[p/3] * rr[p%3];
        float v2 = a[p/3] * uu[p%3];
        #pragma unroll
        for (int o = 16; o; o >>= 1){
            v1 += __shfl_xor_sync(0xffffffffu, v1, o);
            v2 += __shfl_xor_sync(0xffffffffu, v2, o);
        }
        if (lane == p) orv = v1;
        if (lane == p) ouv = v2;
    }
    if (lane < 12){
        out[(size_t)T*12 + lane]           = orv;   // v_r
        out[NTOK*12 + (size_t)T*12 + lane] = ouv;   // v_u
    }
}

// ---------------------------------------------------------------------------
extern "C" void kernel_launch(void* const* d_in, const int* in_sizes, int n_in,
                              void* d_out, int out_size){
    (void)in_sizes; (void)n_in; (void)out_size;
    const float* inv  = (const float*)d_in[0];   // inv_tok (B,N,K,D)
    const float* ego  = (const float*)d_in[1];   // ego_ctx (B,N,256)
    const float* r    = (const float*)d_in[2];   // (B,N,K,3)
    const float* u    = (const float*)d_in[3];   // (B,N,K,3)
    const void*  mask = d_in[4];                 // (B,N,K) bool/int
    const float* We   = (const float*)d_in[5];   // W_ego (256,256)
    const float* be   = (const float*)d_in[6];   // b_ego (256)
    const float* lns  = (const float*)d_in[7];   // ln_scale (256)
    const float* lnb  = (const float*)d_in[8];   // ln_bias (256)
    const float* Wh   = (const float*)d_in[9];   // W_h (512,256)
    const float* bh   = (const float*)d_in[10];  // b_h (256)
    const float* Wl   = (const float*)d_in[11];  // W_logit (256,4)
    // d_in[12] = b_logit: softmax-invariant, unused.

    cudaFuncSetAttribute(k_main,   cudaFuncAttributeMaxDynamicSharedMemorySize, MAIN_SMEM);
    cudaFuncSetAttribute(k_egomma, cudaFuncAttributeMaxDynamicSharedMemorySize, EGO_SMEM);

    k_prep<<<272, 256>>>(Wh, We, be, mask);
    k_egomma<<<NTOK/128, 512, EGO_SMEM>>>(ego, bh);
    k_main<<<2048, 1024, MAIN_SMEM>>>(inv, lns, lnb, Wl);
    k_final<<<NTOK/8, 256>>>(r, u, mask, (float*)d_out);
}

// round 15
// speedup vs baseline: 1.2757x; 1.0280x over previous
#include <cuda_runtime.h>
#include <cuda_bf16.h>
#include <cstdint>
#include <math.h>

// Problem constants
#define NTOK 8192
#define NROWS 262144

// Scratch (static __device__ — no allocations allowed)
__device__ __nv_bfloat16 g_Btb[256*256];   // W_h top, transposed [n][k], bf16
__device__ __nv_bfloat16 g_Wfb[256*256];   // (W_ego @ W_h_bot) transposed [j][e], bf16
__device__ float g_fbpart[8*256];          // partial b_ego @ W_h_bot
__device__ float g_ego[NTOK*256];          // ego contribution (fp32)
__device__ float g_logits[NROWS*4];
__device__ int   g_det[8];                 // mask-is-byte partial flags

__device__ __forceinline__ float wsum(float v){
    #pragma unroll
    for (int o = 16; o; o >>= 1) v += __shfl_xor_sync(0xffffffffu, v, o);
    return v;
}
__device__ __forceinline__ float wmax(float v){
    #pragma unroll
    for (int o = 16; o; o >>= 1) v = fmaxf(v, __shfl_xor_sync(0xffffffffu, v, o));
    return v;
}
__device__ __forceinline__ float fast_tanh(float x){
    float y;
    asm("tanh.approx.f32 %0, %1;" : "=f"(y) : "f"(x));
    return y;
}
__device__ __forceinline__ float gelu_tanh(float x){
    float x3 = x * x * x;
    return 0.5f * x * (1.0f + fast_tanh(0.7978845608028654f * fmaf(0.044715f, x3, x)));
}
__device__ __forceinline__ uint32_t pack_bf2(float a, float b){
    __nv_bfloat162 h = __floats2bfloat162_rn(a, b);   // a -> .x (low)
    return *(uint32_t*)&h;
}

#define MMA_BF16(d, a, b0v, b1v) \
    asm("mma.sync.aligned.m16n8k16.row.col.f32.bf16.bf16.f32 " \
        "{%0,%1,%2,%3}, {%4,%5,%6,%7}, {%8,%9}, {%0,%1,%2,%3};" \
        : "+f"(d[0]), "+f"(d[1]), "+f"(d[2]), "+f"(d[3]) \
        : "r"(a[0]), "r"(a[1]), "r"(a[2]), "r"(a[3]), "r"(b0v), "r"(b1v))

#define LDSM_X4(r0, r1, r2, r3, addr) \
    asm volatile("ldmatrix.sync.aligned.m8n8.x4.shared.b16 {%0,%1,%2,%3}, [%4];" \
        : "=r"(r0), "=r"(r1), "=r"(r2), "=r"(r3) : "r"(addr))

// ---------------------------------------------------------------------------
// k_prep: concurrent roles by blockIdx:
//   0..255   : g_Btb column (bf16 transpose of W_h top) + g_Wfb column
//   256..263 : mask width detect -> g_det
//   264..271 : b_ego @ W_h_bot partials -> g_fbpart
// ---------------------------------------------------------------------------
__global__ void __launch_bounds__(256) k_prep(const float* __restrict__ Wh,
                                              const float* __restrict__ We,
                                              const float* __restrict__ be,
                                              const void*  __restrict__ mask){
    int bid = blockIdx.x, tid = threadIdx.x;
    if (bid < 256){
        g_Btb[bid*256 + tid] = __float2bfloat16(Wh[tid*256 + bid]);
        __shared__ float s[256];
        s[tid] = We[bid*256 + tid];
        __syncthreads();
        float a0=0.f, a1=0.f, a2=0.f, a3=0.f;
        const float* Wb = Wh + 256*256 + tid;
        #pragma unroll 8
        for (int t = 0; t < 256; t += 4){
            a0 = fmaf(s[t],   Wb[(t  )*256], a0);
            a1 = fmaf(s[t+1], Wb[(t+1)*256], a1);
            a2 = fmaf(s[t+2], Wb[(t+2)*256], a2);
            a3 = fmaf(s[t+3], Wb[(t+3)*256], a3);
        }
        g_Wfb[tid*256 + bid] = __float2bfloat16((a0+a1) + (a2+a3));  // [j][e]
    } else if (bid < 264){
        int db = bid - 256;
        __shared__ int f;
        if (tid == 0) f = 0;
        __syncthreads();
        const uint4* m4 = (const uint4*)mask;
        unsigned loc = 0;
        #pragma unroll
        for (int q = 0; q < 8; q++){
            uint4 v = m4[db*2048 + q*256 + tid];
            loc |= (v.x | v.y | v.z | v.w) & 0xFFFFFF00u;
        }
        if (loc) atomicOr(&f, 1);
        __syncthreads();
        if (tid == 0) g_det[db] = f;
    } else {
        int db = bid - 264;
        __shared__ float s[32];
        if (tid < 32) s[tid] = be[db*32 + tid];
        __syncthreads();
        float acc = 0.f;
        const float* Wb = Wh + (256 + db*32)*256 + tid;
        #pragma unroll
        for (int t = 0; t < 32; t++)
            acc = fmaf(s[t], Wb[t*256], acc);
        g_fbpart[db*256 + tid] = acc;
    }
}

// Shared geometry
#define ASTB 264
#define BSTB 24
#define AS_BYTES (128*ASTB*2)        // 67584
#define BS_HALF  (256*BSTB)          // elems per k16 buffer (6144)
#define BS_BYTES (2*BS_HALF*2)       // 24576

// ---------------------------------------------------------------------------
// k_egomma: g_ego = ego_ctx @ Wf + biasc.
// M=64 tiles -> grid 128 (was 64: half the chip sat idle). 512 threads,
// 16 warps as 2M x 8N, warp tile m32 x n32 — byte-identical fragment
// geometry to the measured-optimal k_main inner loop.
// ---------------------------------------------------------------------------
#define EGO_AS_BYTES (64*ASTB*2)     // 33792
#define EGO_SMEM (EGO_AS_BYTES + BS_BYTES + 1024)
__global__ void __launch_bounds__(512, 1) k_egomma(const float* __restrict__ ego,
                                                   const float* __restrict__ bh){
    extern __shared__ char smraw[];
    __nv_bfloat16* As = (__nv_bfloat16*)smraw;
    __nv_bfloat16* Bs = (__nv_bfloat16*)(smraw + EGO_AS_BYTES);
    float* bias_sm    = (float*)(smraw + EGO_AS_BYTES + BS_BYTES);

    int tid = threadIdx.x, lane = tid & 31, wid = tid >> 5;
    int g = lane >> 2, tg = lane & 3;
    int wm = wid >> 3, wn = wid & 7;
    size_t rowbase = (size_t)blockIdx.x * 64;

    if (tid < 256){
        float b = bh[tid];
        #pragma unroll
        for (int q = 0; q < 8; q++) b += g_fbpart[q*256 + tid];
        bias_sm[tid] = b;
    }

    // A convert: warp handles rows wid*4..+3 (64 rows)
    #pragma unroll
    for (int rr = 0; rr < 4; rr++){
        int row = wid*4 + rr;
        const float4* src = (const float4*)(ego + (rowbase + row)*256);
        float4 v0 = src[lane*2], v1 = src[lane*2 + 1];
        uint4 pk;
        pk.x = pack_bf2(v0.x, v0.y);
        pk.y = pack_bf2(v0.z, v0.w);
        pk.z = pack_bf2(v1.x, v1.y);
        pk.w = pack_bf2(v1.z, v1.w);
        *(uint4*)(As + row*ASTB + lane*8) = pk;
    }

    float acc[2][4][4];
    #pragma unroll
    for (int mt = 0; mt < 2; mt++)
        #pragma unroll
        for (int nt = 0; nt < 4; nt++)
            #pragma unroll
            for (int e = 0; e < 4; e++) acc[mt][nt][e] = 0.f;

    // ldmatrix lane addresses (same formulas as k_main)
    uint32_t As_u32 = (uint32_t)__cvta_generic_to_shared(As);
    uint32_t Bs_u32 = (uint32_t)__cvta_generic_to_shared(Bs);
    uint32_t aAddr = As_u32 + ((wm*32 + (lane & 15))*ASTB + ((lane >> 4) << 3)) * 2;
    uint32_t bAddr = Bs_u32 + (((wn*32 + ((lane >> 1) & 8) + (lane & 7))*BSTB
                               + (lane & 8))) * 2;

    // B gmem prefetch: all 512 threads, n = tid>>1, half = tid&1
    const uint4* Bg = (const uint4*)g_Wfb;     // [j][e]: 32 uint4 per row
    int bn = tid >> 1, bhf = tid & 1;
    uint4 pf = Bg[bn*32 + bhf];
    *(uint4*)(Bs + bn*BSTB + bhf*8) = pf;

    for (int ch = 0; ch < 16; ch++){
        __syncthreads();
        if (ch + 1 < 16) pf = Bg[bn*32 + (ch+1)*2 + bhf];
        uint32_t bufB = bAddr + (ch & 1) * (BS_HALF * 2);

        uint32_t a[2][4];
        LDSM_X4(a[0][0], a[0][1], a[0][2], a[0][3], aAddr + ch*32);
        LDSM_X4(a[1][0], a[1][1], a[1][2], a[1][3], aAddr + ch*32 + 16*ASTB*2);

        #pragma unroll
        for (int p = 0; p < 2; p++){
            uint32_t b[4];
            LDSM_X4(b[0], b[1], b[2], b[3], bufB + p*16*BSTB*2);
            #pragma unroll
            for (int q = 0; q < 2; q++){
                int nt = p*2 + q;
                #pragma unroll
                for (int mt = 0; mt < 2; mt++)
                    MMA_BF16(acc[mt][nt], a[mt], b[2*q], b[2*q+1]);
            }
        }
        if (ch + 1 < 16){
            __nv_bfloat16* Bn = Bs + ((ch+1) & 1)*BS_HALF;
            *(uint4*)(Bn + bn*BSTB + bhf*8) = pf;
        }
    }

    // Store: + biasc, fp32. Fragment (mt,nt,hi) -> row wm*32+mt*16+g+8*hi,
    // cols wn*32 + nt*8 + 2*tg (+1).
    #pragma unroll
    for (int mt = 0; mt < 2; mt++)
        #pragma unroll
        for (int nt = 0; nt < 4; nt++){
            int c = wn*32 + nt*8 + 2*tg;
            float bx = bias_sm[c], by = bias_sm[c+1];
            #pragma unroll
            for (int hi = 0; hi < 2; hi++){
                int rrow = wm*32 + mt*16 + g + 8*hi;
                float2 v = make_float2(acc[mt][nt][hi*2] + bx,
                                       acc[mt][nt][hi*2+1] + by);
                *(float2*)&g_ego[(rowbase + rrow)*256 + c] = v;
            }
        }
}

// ---------------------------------------------------------------------------
// k_main: R6 measured-optimal configuration (unchanged from R14 best).
// 1024 threads, 32 warps (4M x 8N), warp tile m32 x n32, ldmatrix.x4,
// k16 chunks with register-prefetch double-buffered B. Fragment-space
// epilogue (+ego, gelu, logits, quad reduce, smem atomics) -> g_logits.
// ---------------------------------------------------------------------------
#define MAIN_SMEM (AS_BYTES + BS_BYTES + 4096 + 2048)
__global__ void __launch_bounds__(1024, 1) k_main(const float* __restrict__ inv,
                                                  const float* __restrict__ lns,
                                                  const float* __restrict__ lnb,
                                                  const float* __restrict__ Wl){
    extern __shared__ char smraw[];
    __nv_bfloat16* As = (__nv_bfloat16*)smraw;
    __nv_bfloat16* Bs = (__nv_bfloat16*)(smraw + AS_BYTES);
    float* Wls        = (float*)(smraw + AS_BYTES + BS_BYTES);          // 1024 f
    float* Lsm        = (float*)(smraw + AS_BYTES + BS_BYTES + 4096);   // 512 f

    int tid = threadIdx.x, lane = tid & 31, wid = tid >> 5;
    int g = lane >> 2, tg = lane & 3;
    int wm = wid >> 3, wn = wid & 7;
    size_t rowbase = (size_t)blockIdx.x * 128;

    Wls[tid] = Wl[tid];
    if (tid < 512) Lsm[tid] = 0.f;

    // LN scale/bias for this lane's 8-element slice
    const float4* lns4 = (const float4*)lns;
    const float4* lnb4 = (const float4*)lnb;
    float4 sc0 = lns4[lane*2], sc1 = lns4[lane*2 + 1];
    float4 sb0 = lnb4[lane*2], sb1 = lnb4[lane*2 + 1];

    // LN pre-pass: warp handles rows wid*4..+3
    #pragma unroll
    for (int rr = 0; rr < 4; rr++){
        int row = wid*4 + rr;
        const float4* src = (const float4*)(inv + (rowbase + row)*256);
        float4 v0 = src[lane*2], v1 = src[lane*2 + 1];
        float s = v0.x+v0.y+v0.z+v0.w + v1.x+v1.y+v1.z+v1.w;
        float q = v0.x*v0.x+v0.y*v0.y+v0.z*v0.z+v0.w*v0.w
                + v1.x*v1.x+v1.y*v1.y+v1.z*v1.z+v1.w*v1.w;
        s = wsum(s); q = wsum(q);
        float mean = s * (1.f/256.f);
        float var  = q * (1.f/256.f) - mean*mean;
        float rstd = rsqrtf(var + 1e-6f);
        uint4 pk;
        pk.x = pack_bf2((v0.x-mean)*rstd*sc0.x + sb0.x, (v0.y-mean)*rstd*sc0.y + sb0.y);
        pk.y = pack_bf2((v0.z-mean)*rstd*sc0.z + sb0.z, (v0.w-mean)*rstd*sc0.w + sb0.w);
        pk.z = pack_bf2((v1.x-mean)*rstd*sc1.x + sb1.x, (v1.y-mean)*rstd*sc1.y + sb1.y);
        pk.w = pack_bf2((v1.z-mean)*rstd*sc1.z + sb1.z, (v1.w-mean)*rstd*sc1.w + sb1.w);
        *(uint4*)(As + row*ASTB + lane*8) = pk;
    }

    float acc[2][4][4];
    #pragma unroll
    for (int mt = 0; mt < 2; mt++)
        #pragma unroll
        for (int nt = 0; nt < 4; nt++)
            #pragma unroll
            for (int e = 0; e < 4; e++) acc[mt][nt][e] = 0.f;

    // ldmatrix lane addresses
    uint32_t As_u32 = (uint32_t)__cvta_generic_to_shared(As);
    uint32_t Bs_u32 = (uint32_t)__cvta_generic_to_shared(Bs);
    uint32_t aAddr = As_u32 + ((wm*32 + (lane & 15))*ASTB + ((lane >> 4) << 3)) * 2;
    uint32_t bAddr = Bs_u32 + (((wn*32 + ((lane >> 1) & 8) + (lane & 7))*BSTB
                               + (lane & 8))) * 2;

    // B gmem prefetch: tid<512; n = tid>>1, half = tid&1
    const uint4* Bg = (const uint4*)g_Btb;
    int bn = tid >> 1, bhf = tid & 1;
    uint4 pf;
    if (tid < 512){
        pf = Bg[bn*32 + bhf];
        *(uint4*)(Bs + bn*BSTB + bhf*8) = pf;
    }

    for (int ch = 0; ch < 16; ch++){
        __syncthreads();
        if (tid < 512 && ch + 1 < 16) pf = Bg[bn*32 + (ch+1)*2 + bhf];
        uint32_t bufB = bAddr + (ch & 1) * (BS_HALF * 2);

        uint32_t a[2][4];
        LDSM_X4(a[0][0], a[0][1], a[0][2], a[0][3], aAddr + ch*32);
        LDSM_X4(a[1][0], a[1][1], a[1][2], a[1][3], aAddr + ch*32 + 16*ASTB*2);

        #pragma unroll
        for (int p = 0; p < 2; p++){
            uint32_t b[4];
            LDSM_X4(b[0], b[1], b[2], b[3], bufB + p*16*BSTB*2);
            #pragma unroll
            for (int q = 0; q < 2; q++){
                int nt = p*2 + q;
                #pragma unroll
                for (int mt = 0; mt < 2; mt++)
                    MMA_BF16(acc[mt][nt], a[mt], b[2*q], b[2*q+1]);
            }
        }
        if (tid < 512 && ch + 1 < 16){
            __nv_bfloat16* Bn = Bs + ((ch+1) & 1)*BS_HALF;
            *(uint4*)(Bn + bn*BSTB + bhf*8) = pf;
        }
    }

    // Fragment-space epilogue: warp wm owns token blockIdx*4 + wm
    size_t token = (size_t)blockIdx.x*4 + wm;
    const float* egorow = g_ego + token*256;

    float pl[4][4];
    #pragma unroll
    for (int i = 0; i < 4; i++)
        #pragma unroll
        for (int h = 0; h < 4; h++) pl[i][h] = 0.f;

    #pragma unroll
    for (int nt = 0; nt < 4; nt++){
        int c = wn*32 + nt*8 + 2*tg;
        float2 eg = *(const float2*)(egorow + c);
        float4 w0 = *(const float4*)(Wls + c*4);
        float4 w1 = *(const float4*)(Wls + (c+1)*4);
        #pragma unroll
        for (int mt = 0; mt < 2; mt++)
            #pragma unroll
            for (int hi = 0; hi < 2; hi++){
                float gl0 = gelu_tanh(acc[mt][nt][hi*2]   + eg.x);
                float gl1 = gelu_tanh(acc[mt][nt][hi*2+1] + eg.y);
                int ri = mt*2 + hi;
                pl[ri][0] = fmaf(gl0, w0.x, fmaf(gl1, w1.x, pl[ri][0]));
                pl[ri][1] = fmaf(gl0, w0.y, fmaf(gl1, w1.y, pl[ri][1]));
                pl[ri][2] = fmaf(gl0, w0.z, fmaf(gl1, w1.z, pl[ri][2]));
                pl[ri][3] = fmaf(gl0, w0.w, fmaf(gl1, w1.w, pl[ri][3]));
            }
    }
    // reduce over the 4 lanes of each quad
    #pragma unroll
    for (int o = 1; o <= 2; o <<= 1)
        #pragma unroll
        for (int ri = 0; ri < 4; ri++)
            #pragma unroll
            for (int h = 0; h < 4; h++)
                pl[ri][h] += __shfl_xor_sync(0xffffffffu, pl[ri][h], o);

    if (tg == 0){
        #pragma unroll
        for (int mt = 0; mt < 2; mt++)
            #pragma unroll
            for (int hi = 0; hi < 2; hi++){
                int rrow = wm*32 + mt*16 + g + 8*hi;
                #pragma unroll
                for (int h = 0; h < 4; h++)
                    atomicAdd(&Lsm[rrow*4 + h], pl[mt*2+hi][h]);
            }
    }
    __syncthreads();
    if (tid < 512)
        g_logits[(rowbase + (tid >> 2))*4 + (tid & 3)] = Lsm[tid];
}

// ---------------------------------------------------------------------------
// k_final: masked softmax over K per head + alpha-weighted r/u reductions.
// ---------------------------------------------------------------------------
__global__ void __launch_bounds__(256) k_final(const float* __restrict__ r,
                                               const float* __restrict__ u,
                                               const void* __restrict__ mask,
                                               float* __restrict__ out){
    __shared__ int s_mb;
    int tid = threadIdx.x, lane = tid & 31, w = tid >> 5;
    if (tid == 0){
        int mb = 0;
        #pragma unroll
        for (int q = 0; q < 8; q++) mb |= g_det[q];
        s_mb = mb;
    }
    __syncthreads();
    int T = blockIdx.x * 8 + w;
    size_t row = (size_t)T * 32 + lane;

    float4 l4 = ((const float4*)g_logits)[row];
    float l[4] = {l4.x, l4.y, l4.z, l4.w};

    bool m;
    if (s_mb) m = ((const unsigned char*)mask)[row] != 0;
    else      m = ((const unsigned int*)mask)[row] != 0u;

    float a[4];
    #pragma unroll
    for (int h = 0; h < 4; h++){
        float v = m ? l[h] : -3.402823466e38f;
        float mx = wmax(v);
        float e  = m ? __expf(l[h] - mx) : 0.f;
        float s  = wsum(e);
        a[h] = (s > 0.f) ? (e / s) : 0.f;
    }

    float* alpha_out = out + 2 * (NTOK * 12);
    ((float4*)alpha_out)[row] = make_float4(a[0], a[1], a[2], a[3]);

    float rr[3], uu[3];
    #pragma unroll
    for (int d = 0; d < 3; d++){
        rr[d] = r[row*3 + d];
        uu[d] = u[row*3 + d];
    }

    float orv = 0.f, ouv = 0.f;
    #pragma unroll
    for (int p = 0; p < 12; p++){
        float v1 = a[p/3] * rr[p%3];
        float v2 = a[p/3] * uu[p%3];
        #pragma unroll
        for (int o = 16; o; o >>= 1){
            v1 += __shfl_xor_sync(0xffffffffu, v1, o);
            v2 += __shfl_xor_sync(0xffffffffu, v2, o);
        }
        if (lane == p) orv = v1;
        if (lane == p) ouv = v2;
    }
    if (lane < 12){
        out[(size_t)T*12 + lane]           = orv;   // v_r
        out[NTOK*12 + (size_t)T*12 + lane] = ouv;   // v_u
    }
}

// ---------------------------------------------------------------------------
extern "C" void kernel_launch(void* const* d_in, const int* in_sizes, int n_in,
                              void* d_out, int out_size){
    (void)in_sizes; (void)n_in; (void)out_size;
    const float* inv  = (const float*)d_in[0];   // inv_tok (B,N,K,D)
    const float* ego  = (const float*)d_in[1];   // ego_ctx (B,N,256)
    const float* r    = (const float*)d_in[2];   // (B,N,K,3)
    const float* u    = (const float*)d_in[3];   // (B,N,K,3)
    const void*  mask = d_in[4];                 // (B,N,K) bool/int
    const float* We   = (const float*)d_in[5];   // W_ego (256,256)
    const float* be   = (const float*)d_in[6];   // b_ego (256)
    const float* lns  = (const float*)d_in[7];   // ln_scale (256)
    const float* lnb  = (const float*)d_in[8];   // ln_bias (256)
    const float* Wh   = (const float*)d_in[9];   // W_h (512,256)
    const float* bh   = (const float*)d_in[10];  // b_h (256)
    const float* Wl   = (const float*)d_in[11];  // W_logit (256,4)
    // d_in[12] = b_logit: softmax-invariant, unused.

    cudaFuncSetAttribute(k_main,   cudaFuncAttributeMaxDynamicSharedMemorySize, MAIN_SMEM);
    cudaFuncSetAttribute(k_egomma, cudaFuncAttributeMaxDynamicSharedMemorySize, EGO_SMEM);

    k_prep<<<272, 256>>>(Wh, We, be, mask);
    k_egomma<<<NTOK/64, 512, EGO_SMEM>>>(ego, bh);
    k_main<<<2048, 1024, MAIN_SMEM>>>(inv, lns, lnb, Wl);
    k_final<<<NTOK/8, 256>>>(r, u, mask, (float*)d_out);
}

// round 16
// speedup vs baseline: 1.2873x; 1.0091x over previous
#include <cuda_runtime.h>
#include <cuda_bf16.h>
#include <cstdint>
#include <math.h>

// Problem constants
#define NTOK 8192
#define NROWS 262144

// Scratch (static __device__ — no allocations allowed)
__device__ __nv_bfloat16 g_Btb[256*256];   // W_h top, transposed [n][k], bf16
__device__ __nv_bfloat16 g_Wfb[256*256];   // (W_ego @ W_h_bot) transposed [j][e], bf16
__device__ float g_fbpart[8*256];          // partial b_ego @ W_h_bot
__device__ float g_ego[NTOK*256];          // ego contribution (fp32)
__device__ float g_logits[NROWS*4];
__device__ int   g_det[8];                 // mask-is-byte partial flags

__device__ __forceinline__ float wsum(float v){
    #pragma unroll
    for (int o = 16; o; o >>= 1) v += __shfl_xor_sync(0xffffffffu, v, o);
    return v;
}
__device__ __forceinline__ float wmax(float v){
    #pragma unroll
    for (int o = 16; o; o >>= 1) v = fmaxf(v, __shfl_xor_sync(0xffffffffu, v, o));
    return v;
}
__device__ __forceinline__ float fast_tanh(float x){
    float y;
    asm("tanh.approx.f32 %0, %1;" : "=f"(y) : "f"(x));
    return y;
}
__device__ __forceinline__ float gelu_tanh(float x){
    float x3 = x * x * x;
    return 0.5f * x * (1.0f + fast_tanh(0.7978845608028654f * fmaf(0.044715f, x3, x)));
}
__device__ __forceinline__ uint32_t pack_bf2(float a, float b){
    __nv_bfloat162 h = __floats2bfloat162_rn(a, b);   // a -> .x (low)
    return *(uint32_t*)&h;
}

#define MMA_BF16(d, a, b0v, b1v) \
    asm("mma.sync.aligned.m16n8k16.row.col.f32.bf16.bf16.f32 " \
        "{%0,%1,%2,%3}, {%4,%5,%6,%7}, {%8,%9}, {%0,%1,%2,%3};" \
        : "+f"(d[0]), "+f"(d[1]), "+f"(d[2]), "+f"(d[3]) \
        : "r"(a[0]), "r"(a[1]), "r"(a[2]), "r"(a[3]), "r"(b0v), "r"(b1v))

#define LDSM_X4(r0, r1, r2, r3, addr) \
    asm volatile("ldmatrix.sync.aligned.m8n8.x4.shared.b16 {%0,%1,%2,%3}, [%4];" \
        : "=r"(r0), "=r"(r1), "=r"(r2), "=r"(r3) : "r"(addr))

// ---------------------------------------------------------------------------
// k_prep: concurrent roles by blockIdx:
//   0..255   : g_Btb column (bf16 transpose of W_h top) + g_Wfb column
//   256..263 : mask width detect -> g_det
//   264..271 : b_ego @ W_h_bot partials -> g_fbpart
// ---------------------------------------------------------------------------
__global__ void __launch_bounds__(256) k_prep(const float* __restrict__ Wh,
                                              const float* __restrict__ We,
                                              const float* __restrict__ be,
                                              const void*  __restrict__ mask){
    int bid = blockIdx.x, tid = threadIdx.x;
    if (bid < 256){
        g_Btb[bid*256 + tid] = __float2bfloat16(Wh[tid*256 + bid]);
        __shared__ float s[256];
        s[tid] = We[bid*256 + tid];
        __syncthreads();
        float a0=0.f, a1=0.f, a2=0.f, a3=0.f;
        const float* Wb = Wh + 256*256 + tid;
        #pragma unroll 8
        for (int t = 0; t < 256; t += 4){
            a0 = fmaf(s[t],   Wb[(t  )*256], a0);
            a1 = fmaf(s[t+1], Wb[(t+1)*256], a1);
            a2 = fmaf(s[t+2], Wb[(t+2)*256], a2);
            a3 = fmaf(s[t+3], Wb[(t+3)*256], a3);
        }
        g_Wfb[tid*256 + bid] = __float2bfloat16((a0+a1) + (a2+a3));  // [j][e]
    } else if (bid < 264){
        int db = bid - 256;
        __shared__ int f;
        if (tid == 0) f = 0;
        __syncthreads();
        const uint4* m4 = (const uint4*)mask;
        unsigned loc = 0;
        #pragma unroll
        for (int q = 0; q < 8; q++){
            uint4 v = m4[db*2048 + q*256 + tid];
            loc |= (v.x | v.y | v.z | v.w) & 0xFFFFFF00u;
        }
        if (loc) atomicOr(&f, 1);
        __syncthreads();
        if (tid == 0) g_det[db] = f;
    } else {
        int db = bid - 264;
        __shared__ float s[32];
        if (tid < 32) s[tid] = be[db*32 + tid];
        __syncthreads();
        float acc = 0.f;
        const float* Wb = Wh + (256 + db*32)*256 + tid;
        #pragma unroll
        for (int t = 0; t < 32; t++)
            acc = fmaf(s[t], Wb[t*256], acc);
        g_fbpart[db*256 + tid] = acc;
    }
}

// Shared geometry
#define ASTB 264
#define BSTB 24
#define AS_BYTES (128*ASTB*2)        // 67584
#define BS_HALF  (256*BSTB)          // elems per k16 buffer (6144)
#define BS_BYTES (2*BS_HALF*2)       // 24576  (k_egomma double buffer)
#define BCH_ELEM (256*BSTB)          // elems per k16 chunk (6144)
#define BCH_BYTES (BCH_ELEM*2)       // 12288

// ---------------------------------------------------------------------------
// k_egomma: g_ego = ego_ctx @ Wf + biasc. M=64 tiles, grid 128, 512 threads,
// 16 warps as 2M x 8N, warp tile m32 x n32 (R15 measured-good version).
// ---------------------------------------------------------------------------
#define EGO_AS_BYTES (64*ASTB*2)     // 33792
#define EGO_SMEM (EGO_AS_BYTES + BS_BYTES + 1024)
__global__ void __launch_bounds__(512, 1) k_egomma(const float* __restrict__ ego,
                                                   const float* __restrict__ bh){
    extern __shared__ char smraw[];
    __nv_bfloat16* As = (__nv_bfloat16*)smraw;
    __nv_bfloat16* Bs = (__nv_bfloat16*)(smraw + EGO_AS_BYTES);
    float* bias_sm    = (float*)(smraw + EGO_AS_BYTES + BS_BYTES);

    int tid = threadIdx.x, lane = tid & 31, wid = tid >> 5;
    int g = lane >> 2, tg = lane & 3;
    int wm = wid >> 3, wn = wid & 7;
    size_t rowbase = (size_t)blockIdx.x * 64;

    if (tid < 256){
        float b = bh[tid];
        #pragma unroll
        for (int q = 0; q < 8; q++) b += g_fbpart[q*256 + tid];
        bias_sm[tid] = b;
    }

    // A convert: warp handles rows wid*4..+3 (64 rows)
    #pragma unroll
    for (int rr = 0; rr < 4; rr++){
        int row = wid*4 + rr;
        const float4* src = (const float4*)(ego + (rowbase + row)*256);
        float4 v0 = src[lane*2], v1 = src[lane*2 + 1];
        uint4 pk;
        pk.x = pack_bf2(v0.x, v0.y);
        pk.y = pack_bf2(v0.z, v0.w);
        pk.z = pack_bf2(v1.x, v1.y);
        pk.w = pack_bf2(v1.z, v1.w);
        *(uint4*)(As + row*ASTB + lane*8) = pk;
    }

    float acc[2][4][4];
    #pragma unroll
    for (int mt = 0; mt < 2; mt++)
        #pragma unroll
        for (int nt = 0; nt < 4; nt++)
            #pragma unroll
            for (int e = 0; e < 4; e++) acc[mt][nt][e] = 0.f;

    uint32_t As_u32 = (uint32_t)__cvta_generic_to_shared(As);
    uint32_t Bs_u32 = (uint32_t)__cvta_generic_to_shared(Bs);
    uint32_t aAddr = As_u32 + ((wm*32 + (lane & 15))*ASTB + ((lane >> 4) << 3)) * 2;
    uint32_t bAddr = Bs_u32 + (((wn*32 + ((lane >> 1) & 8) + (lane & 7))*BSTB
                               + (lane & 8))) * 2;

    const uint4* Bg = (const uint4*)g_Wfb;     // [j][e]: 32 uint4 per row
    int bn = tid >> 1, bhf = tid & 1;
    uint4 pf = Bg[bn*32 + bhf];
    *(uint4*)(Bs + bn*BSTB + bhf*8) = pf;

    for (int ch = 0; ch < 16; ch++){
        __syncthreads();
        if (ch + 1 < 16) pf = Bg[bn*32 + (ch+1)*2 + bhf];
        uint32_t bufB = bAddr + (ch & 1) * (BS_HALF * 2);

        uint32_t a[2][4];
        LDSM_X4(a[0][0], a[0][1], a[0][2], a[0][3], aAddr + ch*32);
        LDSM_X4(a[1][0], a[1][1], a[1][2], a[1][3], aAddr + ch*32 + 16*ASTB*2);

        #pragma unroll
        for (int p = 0; p < 2; p++){
            uint32_t b[4];
            LDSM_X4(b[0], b[1], b[2], b[3], bufB + p*16*BSTB*2);
            #pragma unroll
            for (int q = 0; q < 2; q++){
                int nt = p*2 + q;
                #pragma unroll
                for (int mt = 0; mt < 2; mt++)
                    MMA_BF16(acc[mt][nt], a[mt], b[2*q], b[2*q+1]);
            }
        }
        if (ch + 1 < 16){
            __nv_bfloat16* Bn = Bs + ((ch+1) & 1)*BS_HALF;
            *(uint4*)(Bn + bn*BSTB + bhf*8) = pf;
        }
    }

    #pragma unroll
    for (int mt = 0; mt < 2; mt++)
        #pragma unroll
        for (int nt = 0; nt < 4; nt++){
            int c = wn*32 + nt*8 + 2*tg;
            float bx = bias_sm[c], by = bias_sm[c+1];
            #pragma unroll
            for (int hi = 0; hi < 2; hi++){
                int rrow = wm*32 + mt*16 + g + 8*hi;
                float2 v = make_float2(acc[mt][nt][hi*2] + bx,
                                       acc[mt][nt][hi*2+1] + by);
                *(float2*)&g_ego[(rowbase + rrow)*256 + c] = v;
            }
        }
}

// ---------------------------------------------------------------------------
// k_main: R6 tile geometry (1024 threads, 32 warps 4M x 8N, m32n32,
// ldmatrix.x4), but B staged in k32 stages (2 chunks) with register-prefetch
// double buffering across ALL 1024 threads -> 8 barriers instead of 16.
// Fragment-space epilogue -> g_logits (unchanged).
// SMEM: As 67584 | B 4*12288=49152 | Wl 4096 | Lsm 2048 = 122880
// ---------------------------------------------------------------------------
#define MB_BYTES (4*BCH_BYTES)                        // 49152
#define MAIN_SMEM (AS_BYTES + MB_BYTES + 4096 + 2048) // 122880
__global__ void __launch_bounds__(1024, 1) k_main(const float* __restrict__ inv,
                                                  const float* __restrict__ lns,
                                                  const float* __restrict__ lnb,
                                                  const float* __restrict__ Wl){
    extern __shared__ char smraw[];
    __nv_bfloat16* As = (__nv_bfloat16*)smraw;
    __nv_bfloat16* Bs = (__nv_bfloat16*)(smraw + AS_BYTES);
    float* Wls        = (float*)(smraw + AS_BYTES + MB_BYTES);          // 1024 f
    float* Lsm        = (float*)(smraw + AS_BYTES + MB_BYTES + 4096);   // 512 f

    int tid = threadIdx.x, lane = tid & 31, wid = tid >> 5;
    int g = lane >> 2, tg = lane & 3;
    int wm = wid >> 3, wn = wid & 7;
    size_t rowbase = (size_t)blockIdx.x * 128;

    Wls[tid] = Wl[tid];
    if (tid < 512) Lsm[tid] = 0.f;

    // LN scale/bias for this lane's 8-element slice
    const float4* lns4 = (const float4*)lns;
    const float4* lnb4 = (const float4*)lnb;
    float4 sc0 = lns4[lane*2], sc1 = lns4[lane*2 + 1];
    float4 sb0 = lnb4[lane*2], sb1 = lnb4[lane*2 + 1];

    // LN pre-pass: warp handles rows wid*4..+3
    #pragma unroll
    for (int rr = 0; rr < 4; rr++){
        int row = wid*4 + rr;
        const float4* src = (const float4*)(inv + (rowbase + row)*256);
        float4 v0 = src[lane*2], v1 = src[lane*2 + 1];
        float s = v0.x+v0.y+v0.z+v0.w + v1.x+v1.y+v1.z+v1.w;
        float q = v0.x*v0.x+v0.y*v0.y+v0.z*v0.z+v0.w*v0.w
                + v1.x*v1.x+v1.y*v1.y+v1.z*v1.z+v1.w*v1.w;
        s = wsum(s); q = wsum(q);
        float mean = s * (1.f/256.f);
        float var  = q * (1.f/256.f) - mean*mean;
        float rstd = rsqrtf(var + 1e-6f);
        uint4 pk;
        pk.x = pack_bf2((v0.x-mean)*rstd*sc0.x + sb0.x, (v0.y-mean)*rstd*sc0.y + sb0.y);
        pk.y = pack_bf2((v0.z-mean)*rstd*sc0.z + sb0.z, (v0.w-mean)*rstd*sc0.w + sb0.w);
        pk.z = pack_bf2((v1.x-mean)*rstd*sc1.x + sb1.x, (v1.y-mean)*rstd*sc1.y + sb1.y);
        pk.w = pack_bf2((v1.z-mean)*rstd*sc1.z + sb1.z, (v1.w-mean)*rstd*sc1.w + sb1.w);
        *(uint4*)(As + row*ASTB + lane*8) = pk;
    }

    float acc[2][4][4];
    #pragma unroll
    for (int mt = 0; mt < 2; mt++)
        #pragma unroll
        for (int nt = 0; nt < 4; nt++)
            #pragma unroll
            for (int e = 0; e < 4; e++) acc[mt][nt][e] = 0.f;

    // ldmatrix lane addresses
    uint32_t As_u32 = (uint32_t)__cvta_generic_to_shared(As);
    uint32_t Bs_u32 = (uint32_t)__cvta_generic_to_shared(Bs);
    uint32_t aAddr = As_u32 + ((wm*32 + (lane & 15))*ASTB + ((lane >> 4) << 3)) * 2;
    uint32_t bAddr = Bs_u32 + (((wn*32 + ((lane >> 1) & 8) + (lane & 7))*BSTB
                               + (lane & 8))) * 2;

    // B stage prefetch: all 1024 threads, 1 uint4 each per k32 stage.
    // Granule: chunk-within-stage c = tid>>9, n = (tid>>1)&255, half = tid&1.
    // Source for stage s: Bg[n*32 + (2s + c)*2 + half].
    const uint4* Bg = (const uint4*)g_Btb;
    int sc = tid >> 9, bn = (tid >> 1) & 255, bhf = tid & 1;
    __nv_bfloat16* dst0 = Bs + sc*BCH_ELEM + bn*BSTB + bhf*8;   // stage buffer 0
    __nv_bfloat16* dst1 = dst0 + 2*BCH_ELEM;                     // stage buffer 1
    const uint4* srcg = Bg + bn*32 + sc*2 + bhf;                 // + stage*4

    uint4 pf = srcg[0];
    *(uint4*)dst0 = pf;

    for (int s = 0; s < 8; s++){
        __syncthreads();
        if (s + 1 < 8) pf = srcg[(s+1)*4];
        uint32_t stageB = bAddr + (s & 1) * (2*BCH_BYTES);

        #pragma unroll
        for (int sub = 0; sub < 2; sub++){
            int ch = s*2 + sub;
            uint32_t a[2][4];
            LDSM_X4(a[0][0], a[0][1], a[0][2], a[0][3], aAddr + ch*32);
            LDSM_X4(a[1][0], a[1][1], a[1][2], a[1][3], aAddr + ch*32 + 16*ASTB*2);

            #pragma unroll
            for (int p = 0; p < 2; p++){
                uint32_t b[4];
                LDSM_X4(b[0], b[1], b[2], b[3],
                        stageB + sub*BCH_BYTES + p*16*BSTB*2);
                #pragma unroll
                for (int q = 0; q < 2; q++){
                    int nt = p*2 + q;
                    #pragma unroll
                    for (int mt = 0; mt < 2; mt++)
                        MMA_BF16(acc[mt][nt], a[mt], b[2*q], b[2*q+1]);
                }
            }
        }
        if (s + 1 < 8)
            *(uint4*)(((s+1) & 1) ? dst1 : dst0) = pf;
    }

    // Fragment-space epilogue: warp wm owns token blockIdx*4 + wm
    size_t token = (size_t)blockIdx.x*4 + wm;
    const float* egorow = g_ego + token*256;

    float pl[4][4];
    #pragma unroll
    for (int i = 0; i < 4; i++)
        #pragma unroll
        for (int h = 0; h < 4; h++) pl[i][h] = 0.f;

    #pragma unroll
    for (int nt = 0; nt < 4; nt++){
        int c = wn*32 + nt*8 + 2*tg;
        float2 eg = *(const float2*)(egorow + c);
        float4 w0 = *(const float4*)(Wls + c*4);
        float4 w1 = *(const float4*)(Wls + (c+1)*4);
        #pragma unroll
        for (int mt = 0; mt < 2; mt++)
            #pragma unroll
            for (int hi = 0; hi < 2; hi++){
                float gl0 = gelu_tanh(acc[mt][nt][hi*2]   + eg.x);
                float gl1 = gelu_tanh(acc[mt][nt][hi*2+1] + eg.y);
                int ri = mt*2 + hi;
                pl[ri][0] = fmaf(gl0, w0.x, fmaf(gl1, w1.x, pl[ri][0]));
                pl[ri][1] = fmaf(gl0, w0.y, fmaf(gl1, w1.y, pl[ri][1]));
                pl[ri][2] = fmaf(gl0, w0.z, fmaf(gl1, w1.z, pl[ri][2]));
                pl[ri][3] = fmaf(gl0, w0.w, fmaf(gl1, w1.w, pl[ri][3]));
            }
    }
    // reduce over the 4 lanes of each quad
    #pragma unroll
    for (int o = 1; o <= 2; o <<= 1)
        #pragma unroll
        for (int ri = 0; ri < 4; ri++)
            #pragma unroll
            for (int h = 0; h < 4; h++)
                pl[ri][h] += __shfl_xor_sync(0xffffffffu, pl[ri][h], o);

    if (tg == 0){
        #pragma unroll
        for (int mt = 0; mt < 2; mt++)
            #pragma unroll
            for (int hi = 0; hi < 2; hi++){
                int rrow = wm*32 + mt*16 + g + 8*hi;
                #pragma unroll
                for (int h = 0; h < 4; h++)
                    atomicAdd(&Lsm[rrow*4 + h], pl[mt*2+hi][h]);
            }
    }
    __syncthreads();
    if (tid < 512)
        g_logits[(rowbase + (tid >> 2))*4 + (tid & 3)] = Lsm[tid];
}

// ---------------------------------------------------------------------------
// k_final: masked softmax over K per head + alpha-weighted r/u reductions.
// ---------------------------------------------------------------------------
__global__ void __launch_bounds__(256) k_final(const float* __restrict__ r,
                                               const float* __restrict__ u,
                                               const void* __restrict__ mask,
                                               float* __restrict__ out){
    __shared__ int s_mb;
    int tid = threadIdx.x, lane = tid & 31, w = tid >> 5;
    if (tid == 0){
        int mb = 0;
        #pragma unroll
        for (int q = 0; q < 8; q++) mb |= g_det[q];
        s_mb = mb;
    }
    __syncthreads();
    int T = blockIdx.x * 8 + w;
    size_t row = (size_t)T * 32 + lane;

    float4 l4 = ((const float4*)g_logits)[row];
    float l[4] = {l4.x, l4.y, l4.z, l4.w};

    bool m;
    if (s_mb) m = ((const unsigned char*)mask)[row] != 0;
    else      m = ((const unsigned int*)mask)[row] != 0u;

    float a[4];
    #pragma unroll
    for (int h = 0; h < 4; h++){
        float v = m ? l[h] : -3.402823466e38f;
        float mx = wmax(v);
        float e  = m ? __expf(l[h] - mx) : 0.f;
        float s  = wsum(e);
        a[h] = (s > 0.f) ? (e / s) : 0.f;
    }

    float* alpha_out = out + 2 * (NTOK * 12);
    ((float4*)alpha_out)[row] = make_float4(a[0], a[1], a[2], a[3]);

    float rr[3], uu[3];
    #pragma unroll
    for (int d = 0; d < 3; d++){
        rr[d] = r[row*3 + d];
        uu[d] = u[row*3 + d];
    }

    float orv = 0.f, ouv = 0.f;
    #pragma unroll
    for (int p = 0; p < 12; p++){
        float v1 = a[p/3] * rr[p%3];
        float v2 = a[p/3] * uu[p%3];
        #pragma unroll
        for (int o = 16; o; o >>= 1){
            v1 += __shfl_xor_sync(0xffffffffu, v1, o);
            v2 += __shfl_xor_sync(0xffffffffu, v2, o);
        }
        if (lane == p) orv = v1;
        if (lane == p) ouv = v2;
    }
    if (lane < 12){
        out[(size_t)T*12 + lane]           = orv;   // v_r
        out[NTOK*12 + (size_t)T*12 + lane] = ouv;   // v_u
    }
}

// ---------------------------------------------------------------------------
extern "C" void kernel_launch(void* const* d_in, const int* in_sizes, int n_in,
                              void* d_out, int out_size){
    (void)in_sizes; (void)n_in; (void)out_size;
    const float* inv  = (const float*)d_in[0];   // inv_tok (B,N,K,D)
    const float* ego  = (const float*)d_in[1];   // ego_ctx (B,N,256)
    const float* r    = (const float*)d_in[2];   // (B,N,K,3)
    const float* u    = (const float*)d_in[3];   // (B,N,K,3)
    const void*  mask = d_in[4];                 // (B,N,K) bool/int
    const float* We   = (const float*)d_in[5];   // W_ego (256,256)
    const float* be   = (const float*)d_in[6];   // b_ego (256)
    const float* lns  = (const float*)d_in[7];   // ln_scale (256)
    const float* lnb  = (const float*)d_in[8];   // ln_bias (256)
    const float* Wh   = (const float*)d_in[9];   // W_h (512,256)
    const float* bh   = (const float*)d_in[10];  // b_h (256)
    const float* Wl   = (const float*)d_in[11];  // W_logit (256,4)
    // d_in[12] = b_logit: softmax-invariant, unused.

    cudaFuncSetAttribute(k_main,   cudaFuncAttributeMaxDynamicSharedMemorySize, MAIN_SMEM);
    cudaFuncSetAttribute(k_egomma, cudaFuncAttributeMaxDynamicSharedMemorySize, EGO_SMEM);

    k_prep<<<272, 256>>>(Wh, We, be, mask);
    k_egomma<<<NTOK/64, 512, EGO_SMEM>>>(ego, bh);
    k_main<<<2048, 1024, MAIN_SMEM>>>(inv, lns, lnb, Wl);
    k_final<<<NTOK/8, 256>>>(r, u, mask, (float*)d_out);
}

// round 17
// speedup vs baseline: 1.3094x; 1.0172x over previous
#include <cuda_runtime.h>
#include <cuda_bf16.h>
#include <cstdint>
#include <math.h>

// Problem constants
#define NTOK 8192
#define NROWS 262144

// Scratch (static __device__ — no allocations allowed)
__device__ __nv_bfloat16 g_Btb[256*256];   // W_h top, transposed [n][k], bf16
__device__ __nv_bfloat16 g_Wfb[256*256];   // (W_ego @ W_h_bot) transposed [j][e], bf16
__device__ float g_fbpart[8*256];          // partial b_ego @ W_h_bot
__device__ float g_ego[NTOK*256];          // ego contribution (fp32)
__device__ float g_logits[NROWS*4];
__device__ int   g_det[8];                 // mask-is-byte partial flags

__device__ __forceinline__ float wsum(float v){
    #pragma unroll
    for (int o = 16; o; o >>= 1) v += __shfl_xor_sync(0xffffffffu, v, o);
    return v;
}
__device__ __forceinline__ float wmax(float v){
    #pragma unroll
    for (int o = 16; o; o >>= 1) v = fmaxf(v, __shfl_xor_sync(0xffffffffu, v, o));
    return v;
}
__device__ __forceinline__ float fast_tanh(float x){
    float y;
    asm("tanh.approx.f32 %0, %1;" : "=f"(y) : "f"(x));
    return y;
}
__device__ __forceinline__ float gelu_tanh(float x){
    float x3 = x * x * x;
    return 0.5f * x * (1.0f + fast_tanh(0.7978845608028654f * fmaf(0.044715f, x3, x)));
}
__device__ __forceinline__ uint32_t pack_bf2(float a, float b){
    __nv_bfloat162 h = __floats2bfloat162_rn(a, b);   // a -> .x (low)
    return *(uint32_t*)&h;
}

#define MMA_BF16(d, a, b0v, b1v) \
    asm("mma.sync.aligned.m16n8k16.row.col.f32.bf16.bf16.f32 " \
        "{%0,%1,%2,%3}, {%4,%5,%6,%7}, {%8,%9}, {%0,%1,%2,%3};" \
        : "+f"(d[0]), "+f"(d[1]), "+f"(d[2]), "+f"(d[3]) \
        : "r"(a[0]), "r"(a[1]), "r"(a[2]), "r"(a[3]), "r"(b0v), "r"(b1v))

#define LDSM_X4(r0, r1, r2, r3, addr) \
    asm volatile("ldmatrix.sync.aligned.m8n8.x4.shared.b16 {%0,%1,%2,%3}, [%4];" \
        : "=r"(r0), "=r"(r1), "=r"(r2), "=r"(r3) : "r"(addr))

// ---------------------------------------------------------------------------
// k_prep: concurrent roles by blockIdx:
//   0..255   : g_Btb column (bf16 transpose of W_h top) + g_Wfb column
//   256..263 : mask width detect -> g_det
//   264..271 : b_ego @ W_h_bot partials -> g_fbpart
// ---------------------------------------------------------------------------
__global__ void __launch_bounds__(256) k_prep(const float* __restrict__ Wh,
                                              const float* __restrict__ We,
                                              const float* __restrict__ be,
                                              const void*  __restrict__ mask){
    int bid = blockIdx.x, tid = threadIdx.x;
    if (bid < 256){
        g_Btb[bid*256 + tid] = __float2bfloat16(Wh[tid*256 + bid]);
        __shared__ float s[256];
        s[tid] = We[bid*256 + tid];
        __syncthreads();
        float a0=0.f, a1=0.f, a2=0.f, a3=0.f;
        const float* Wb = Wh + 256*256 + tid;
        #pragma unroll 8
        for (int t = 0; t < 256; t += 4){
            a0 = fmaf(s[t],   Wb[(t  )*256], a0);
            a1 = fmaf(s[t+1], Wb[(t+1)*256], a1);
            a2 = fmaf(s[t+2], Wb[(t+2)*256], a2);
            a3 = fmaf(s[t+3], Wb[(t+3)*256], a3);
        }
        g_Wfb[tid*256 + bid] = __float2bfloat16((a0+a1) + (a2+a3));  // [j][e]
    } else if (bid < 264){
        int db = bid - 256;
        __shared__ int f;
        if (tid == 0) f = 0;
        __syncthreads();
        const uint4* m4 = (const uint4*)mask;
        unsigned loc = 0;
        #pragma unroll
        for (int q = 0; q < 8; q++){
            uint4 v = m4[db*2048 + q*256 + tid];
            loc |= (v.x | v.y | v.z | v.w) & 0xFFFFFF00u;
        }
        if (loc) atomicOr(&f, 1);
        __syncthreads();
        if (tid == 0) g_det[db] = f;
    } else {
        int db = bid - 264;
        __shared__ float s[32];
        if (tid < 32) s[tid] = be[db*32 + tid];
        __syncthreads();
        float acc = 0.f;
        const float* Wb = Wh + (256 + db*32)*256 + tid;
        #pragma unroll
        for (int t = 0; t < 32; t++)
            acc = fmaf(s[t], Wb[t*256], acc);
        g_fbpart[db*256 + tid] = acc;
    }
}

// Shared geometry
#define ASTB 264
#define BSTB 24
#define AS_BYTES (128*ASTB*2)        // 67584
#define BS_HALF  (256*BSTB)          // elems per k16 buffer (6144)
#define BS_BYTES (2*BS_HALF*2)       // 24576  (k_egomma double buffer)
#define BCH_ELEM (256*BSTB)          // elems per k16 chunk (6144)
#define BCH_BYTES (BCH_ELEM*2)       // 12288

// ---------------------------------------------------------------------------
// k_egomma: g_ego = ego_ctx @ Wf + biasc. M=64 tiles, grid 128, 512 threads,
// 16 warps as 2M x 8N, warp tile m32 x n32 (R15/R16 measured-good version).
// ---------------------------------------------------------------------------
#define EGO_AS_BYTES (64*ASTB*2)     // 33792
#define EGO_SMEM (EGO_AS_BYTES + BS_BYTES + 1024)
__global__ void __launch_bounds__(512, 1) k_egomma(const float* __restrict__ ego,
                                                   const float* __restrict__ bh){
    extern __shared__ char smraw[];
    __nv_bfloat16* As = (__nv_bfloat16*)smraw;
    __nv_bfloat16* Bs = (__nv_bfloat16*)(smraw + EGO_AS_BYTES);
    float* bias_sm    = (float*)(smraw + EGO_AS_BYTES + BS_BYTES);

    int tid = threadIdx.x, lane = tid & 31, wid = tid >> 5;
    int g = lane >> 2, tg = lane & 3;
    int wm = wid >> 3, wn = wid & 7;
    size_t rowbase = (size_t)blockIdx.x * 64;

    if (tid < 256){
        float b = bh[tid];
        #pragma unroll
        for (int q = 0; q < 8; q++) b += g_fbpart[q*256 + tid];
        bias_sm[tid] = b;
    }

    // A convert: warp handles rows wid*4..+3 (64 rows)
    #pragma unroll
    for (int rr = 0; rr < 4; rr++){
        int row = wid*4 + rr;
        const float4* src = (const float4*)(ego + (rowbase + row)*256);
        float4 v0 = src[lane*2], v1 = src[lane*2 + 1];
        uint4 pk;
        pk.x = pack_bf2(v0.x, v0.y);
        pk.y = pack_bf2(v0.z, v0.w);
        pk.z = pack_bf2(v1.x, v1.y);
        pk.w = pack_bf2(v1.z, v1.w);
        *(uint4*)(As + row*ASTB + lane*8) = pk;
    }

    float acc[2][4][4];
    #pragma unroll
    for (int mt = 0; mt < 2; mt++)
        #pragma unroll
        for (int nt = 0; nt < 4; nt++)
            #pragma unroll
            for (int e = 0; e < 4; e++) acc[mt][nt][e] = 0.f;

    uint32_t As_u32 = (uint32_t)__cvta_generic_to_shared(As);
    uint32_t Bs_u32 = (uint32_t)__cvta_generic_to_shared(Bs);
    uint32_t aAddr = As_u32 + ((wm*32 + (lane & 15))*ASTB + ((lane >> 4) << 3)) * 2;
    uint32_t bAddr = Bs_u32 + (((wn*32 + ((lane >> 1) & 8) + (lane & 7))*BSTB
                               + (lane & 8))) * 2;

    const uint4* Bg = (const uint4*)g_Wfb;     // [j][e]: 32 uint4 per row
    int bn = tid >> 1, bhf = tid & 1;
    uint4 pf = Bg[bn*32 + bhf];
    *(uint4*)(Bs + bn*BSTB + bhf*8) = pf;

    for (int ch = 0; ch < 16; ch++){
        __syncthreads();
        if (ch + 1 < 16) pf = Bg[bn*32 + (ch+1)*2 + bhf];
        uint32_t bufB = bAddr + (ch & 1) * (BS_HALF * 2);

        uint32_t a[2][4];
        LDSM_X4(a[0][0], a[0][1], a[0][2], a[0][3], aAddr + ch*32);
        LDSM_X4(a[1][0], a[1][1], a[1][2], a[1][3], aAddr + ch*32 + 16*ASTB*2);

        #pragma unroll
        for (int p = 0; p < 2; p++){
            uint32_t b[4];
            LDSM_X4(b[0], b[1], b[2], b[3], bufB + p*16*BSTB*2);
            #pragma unroll
            for (int q = 0; q < 2; q++){
                int nt = p*2 + q;
                #pragma unroll
                for (int mt = 0; mt < 2; mt++)
                    MMA_BF16(acc[mt][nt], a[mt], b[2*q], b[2*q+1]);
            }
        }
        if (ch + 1 < 16){
            __nv_bfloat16* Bn = Bs + ((ch+1) & 1)*BS_HALF;
            *(uint4*)(Bn + bn*BSTB + bhf*8) = pf;
        }
    }

    #pragma unroll
    for (int mt = 0; mt < 2; mt++)
        #pragma unroll
        for (int nt = 0; nt < 4; nt++){
            int c = wn*32 + nt*8 + 2*tg;
            float bx = bias_sm[c], by = bias_sm[c+1];
            #pragma unroll
            for (int hi = 0; hi < 2; hi++){
                int rrow = wm*32 + mt*16 + g + 8*hi;
                float2 v = make_float2(acc[mt][nt][hi*2] + bx,
                                       acc[mt][nt][hi*2+1] + by);
                *(float2*)&g_ego[(rowbase + rrow)*256 + c] = v;
            }
        }
}

// ---------------------------------------------------------------------------
// k_main: R6 tile geometry (1024 threads, 32 warps 4M x 8N, m32n32,
// ldmatrix.x4), B staged in k64 stages (4 chunks) with register-prefetch
// double buffering across all 1024 threads -> 4 barriers total in mainloop.
// Fragment-space epilogue -> g_logits (unchanged).
// SMEM: As 67584 | B 8*12288=98304 | Wl 4096 | Lsm 2048 = 172032
// ---------------------------------------------------------------------------
#define MB_BYTES (8*BCH_BYTES)                        // 98304
#define MAIN_SMEM (AS_BYTES + MB_BYTES + 4096 + 2048) // 172032
__global__ void __launch_bounds__(1024, 1) k_main(const float* __restrict__ inv,
                                                  const float* __restrict__ lns,
                                                  const float* __restrict__ lnb,
                                                  const float* __restrict__ Wl){
    extern __shared__ char smraw[];
    __nv_bfloat16* As = (__nv_bfloat16*)smraw;
    __nv_bfloat16* Bs = (__nv_bfloat16*)(smraw + AS_BYTES);
    float* Wls        = (float*)(smraw + AS_BYTES + MB_BYTES);          // 1024 f
    float* Lsm        = (float*)(smraw + AS_BYTES + MB_BYTES + 4096);   // 512 f

    int tid = threadIdx.x, lane = tid & 31, wid = tid >> 5;
    int g = lane >> 2, tg = lane & 3;
    int wm = wid >> 3, wn = wid & 7;
    size_t rowbase = (size_t)blockIdx.x * 128;

    Wls[tid] = Wl[tid];
    if (tid < 512) Lsm[tid] = 0.f;

    // LN scale/bias for this lane's 8-element slice
    const float4* lns4 = (const float4*)lns;
    const float4* lnb4 = (const float4*)lnb;
    float4 sc0 = lns4[lane*2], sc1 = lns4[lane*2 + 1];
    float4 sb0 = lnb4[lane*2], sb1 = lnb4[lane*2 + 1];

    // LN pre-pass: warp handles rows wid*4..+3
    #pragma unroll
    for (int rr = 0; rr < 4; rr++){
        int row = wid*4 + rr;
        const float4* src = (const float4*)(inv + (rowbase + row)*256);
        float4 v0 = src[lane*2], v1 = src[lane*2 + 1];
        float s = v0.x+v0.y+v0.z+v0.w + v1.x+v1.y+v1.z+v1.w;
        float q = v0.x*v0.x+v0.y*v0.y+v0.z*v0.z+v0.w*v0.w
                + v1.x*v1.x+v1.y*v1.y+v1.z*v1.z+v1.w*v1.w;
        s = wsum(s); q = wsum(q);
        float mean = s * (1.f/256.f);
        float var  = q * (1.f/256.f) - mean*mean;
        float rstd = rsqrtf(var + 1e-6f);
        uint4 pk;
        pk.x = pack_bf2((v0.x-mean)*rstd*sc0.x + sb0.x, (v0.y-mean)*rstd*sc0.y + sb0.y);
        pk.y = pack_bf2((v0.z-mean)*rstd*sc0.z + sb0.z, (v0.w-mean)*rstd*sc0.w + sb0.w);
        pk.z = pack_bf2((v1.x-mean)*rstd*sc1.x + sb1.x, (v1.y-mean)*rstd*sc1.y + sb1.y);
        pk.w = pack_bf2((v1.z-mean)*rstd*sc1.z + sb1.z, (v1.w-mean)*rstd*sc1.w + sb1.w);
        *(uint4*)(As + row*ASTB + lane*8) = pk;
    }

    float acc[2][4][4];
    #pragma unroll
    for (int mt = 0; mt < 2; mt++)
        #pragma unroll
        for (int nt = 0; nt < 4; nt++)
            #pragma unroll
            for (int e = 0; e < 4; e++) acc[mt][nt][e] = 0.f;

    // ldmatrix lane addresses
    uint32_t As_u32 = (uint32_t)__cvta_generic_to_shared(As);
    uint32_t Bs_u32 = (uint32_t)__cvta_generic_to_shared(Bs);
    uint32_t aAddr = As_u32 + ((wm*32 + (lane & 15))*ASTB + ((lane >> 4) << 3)) * 2;
    uint32_t bAddr = Bs_u32 + (((wn*32 + ((lane >> 1) & 8) + (lane & 7))*BSTB
                               + (lane & 8))) * 2;

    // B stage prefetch: k64 stage = 4 chunks = 2048 granules of 16B.
    // Each of 1024 threads owns 2 granules: gid = tid + q*1024 (q=0,1).
    //   chunk c = gid >> 9 (0..3), w = gid & 511, n = w >> 1, half = w & 1.
    // Source for stage s: Bg[n*32 + (s*4 + c)*2 + half] = base + s*8.
    const uint4* Bg = (const uint4*)g_Btb;
    int c0 = tid >> 9,          w0 = tid & 511;
    int n0 = w0 >> 1,           h0 = w0 & 1;
    int c1 = (tid + 1024) >> 9, w1 = tid & 511;   // gid+1024: chunk +2, same w
    int n1 = w1 >> 1,           h1 = w1 & 1;
    __nv_bfloat16* d0a = Bs + c0*BCH_ELEM + n0*BSTB + h0*8;       // buffer 0
    __nv_bfloat16* d1a = Bs + c1*BCH_ELEM + n1*BSTB + h1*8;
    __nv_bfloat16* d0b = d0a + 4*BCH_ELEM;                        // buffer 1
    __nv_bfloat16* d1b = d1a + 4*BCH_ELEM;
    const uint4* s0 = Bg + n0*32 + c0*2 + h0;                     // + s*8
    const uint4* s1 = Bg + n1*32 + c1*2 + h1;

    uint4 pf0 = s0[0], pf1 = s1[0];
    *(uint4*)d0a = pf0;
    *(uint4*)d1a = pf1;

    for (int s = 0; s < 4; s++){
        __syncthreads();
        if (s + 1 < 4){
            pf0 = s0[(s+1)*8];
            pf1 = s1[(s+1)*8];
        }
        uint32_t stageB = bAddr + (s & 1) * (4*BCH_BYTES);

        #pragma unroll
        for (int sub = 0; sub < 4; sub++){
            int ch = s*4 + sub;
            uint32_t a[2][4];
            LDSM_X4(a[0][0], a[0][1], a[0][2], a[0][3], aAddr + ch*32);
            LDSM_X4(a[1][0], a[1][1], a[1][2], a[1][3], aAddr + ch*32 + 16*ASTB*2);

            #pragma unroll
            for (int p = 0; p < 2; p++){
                uint32_t b[4];
                LDSM_X4(b[0], b[1], b[2], b[3],
                        stageB + sub*BCH_BYTES + p*16*BSTB*2);
                #pragma unroll
                for (int q = 0; q < 2; q++){
                    int nt = p*2 + q;
                    #pragma unroll
                    for (int mt = 0; mt < 2; mt++)
                        MMA_BF16(acc[mt][nt], a[mt], b[2*q], b[2*q+1]);
                }
            }
        }
        if (s + 1 < 4){
            if ((s+1) & 1){ *(uint4*)d0b = pf0; *(uint4*)d1b = pf1; }
            else          { *(uint4*)d0a = pf0; *(uint4*)d1a = pf1; }
        }
    }

    // Fragment-space epilogue: warp wm owns token blockIdx*4 + wm
    size_t token = (size_t)blockIdx.x*4 + wm;
    const float* egorow = g_ego + token*256;

    float pl[4][4];
    #pragma unroll
    for (int i = 0; i < 4; i++)
        #pragma unroll
        for (int h = 0; h < 4; h++) pl[i][h] = 0.f;

    #pragma unroll
    for (int nt = 0; nt < 4; nt++){
        int c = wn*32 + nt*8 + 2*tg;
        float2 eg = *(const float2*)(egorow + c);
        float4 w0v = *(const float4*)(Wls + c*4);
        float4 w1v = *(const float4*)(Wls + (c+1)*4);
        #pragma unroll
        for (int mt = 0; mt < 2; mt++)
            #pragma unroll
            for (int hi = 0; hi < 2; hi++){
                float gl0 = gelu_tanh(acc[mt][nt][hi*2]   + eg.x);
                float gl1 = gelu_tanh(acc[mt][nt][hi*2+1] + eg.y);
                int ri = mt*2 + hi;
                pl[ri][0] = fmaf(gl0, w0v.x, fmaf(gl1, w1v.x, pl[ri][0]));
                pl[ri][1] = fmaf(gl0, w0v.y, fmaf(gl1, w1v.y, pl[ri][1]));
                pl[ri][2] = fmaf(gl0, w0v.z, fmaf(gl1, w1v.z, pl[ri][2]));
                pl[ri][3] = fmaf(gl0, w0v.w, fmaf(gl1, w1v.w, pl[ri][3]));
            }
    }
    // reduce over the 4 lanes of each quad
    #pragma unroll
    for (int o = 1; o <= 2; o <<= 1)
        #pragma unroll
        for (int ri = 0; ri < 4; ri++)
            #pragma unroll
            for (int h = 0; h < 4; h++)
                pl[ri][h] += __shfl_xor_sync(0xffffffffu, pl[ri][h], o);

    if (tg == 0){
        #pragma unroll
        for (int mt = 0; mt < 2; mt++)
            #pragma unroll
            for (int hi = 0; hi < 2; hi++){
                int rrow = wm*32 + mt*16 + g + 8*hi;
                #pragma unroll
                for (int h = 0; h < 4; h++)
                    atomicAdd(&Lsm[rrow*4 + h], pl[mt*2+hi][h]);
            }
    }
    __syncthreads();
    if (tid < 512)
        g_logits[(rowbase + (tid >> 2))*4 + (tid & 3)] = Lsm[tid];
}

// ---------------------------------------------------------------------------
// k_final: masked softmax over K per head + alpha-weighted r/u reductions.
// ---------------------------------------------------------------------------
__global__ void __launch_bounds__(256) k_final(const float* __restrict__ r,
                                               const float* __restrict__ u,
                                               const void* __restrict__ mask,
                                               float* __restrict__ out){
    __shared__ int s_mb;
    int tid = threadIdx.x, lane = tid & 31, w = tid >> 5;
    if (tid == 0){
        int mb = 0;
        #pragma unroll
        for (int q = 0; q < 8; q++) mb |= g_det[q];
        s_mb = mb;
    }
    __syncthreads();
    int T = blockIdx.x * 8 + w;
    size_t row = (size_t)T * 32 + lane;

    float4 l4 = ((const float4*)g_logits)[row];
    float l[4] = {l4.x, l4.y, l4.z, l4.w};

    bool m;
    if (s_mb) m = ((const unsigned char*)mask)[row] != 0;
    else      m = ((const unsigned int*)mask)[row] != 0u;

    float a[4];
    #pragma unroll
    for (int h = 0; h < 4; h++){
        float v = m ? l[h] : -3.402823466e38f;
        float mx = wmax(v);
        float e  = m ? __expf(l[h] - mx) : 0.f;
        float s  = wsum(e);
        a[h] = (s > 0.f) ? (e / s) : 0.f;
    }

    float* alpha_out = out + 2 * (NTOK * 12);
    ((float4*)alpha_out)[row] = make_float4(a[0], a[1], a[2], a[3]);

    float rr[3], uu[3];
    #pragma unroll
    for (int d = 0; d < 3; d++){
        rr[d] = r[row*3 + d];
        uu[d] = u[row*3 + d];
    }

    float orv = 0.f, ouv = 0.f;
    #pragma unroll
    for (int p = 0; p < 12; p++){
        float v1 = a[p/3] * rr[p%3];
        float v2 = a[p/3] * uu[p%3];
        #pragma unroll
        for (int o = 16; o; o >>= 1){
            v1 += __shfl_xor_sync(0xffffffffu, v1, o);
            v2 += __shfl_xor_sync(0xffffffffu, v2, o);
        }
        if (lane == p) orv = v1;
        if (lane == p) ouv = v2;
    }
    if (lane < 12){
        out[(size_t)T*12 + lane]           = orv;   // v_r
        out[NTOK*12 + (size_t)T*12 + lane] = ouv;   // v_u
    }
}

// ---------------------------------------------------------------------------
extern "C" void kernel_launch(void* const* d_in, const int* in_sizes, int n_in,
                              void* d_out, int out_size){
    (void)in_sizes; (void)n_in; (void)out_size;
    const float* inv  = (const float*)d_in[0];   // inv_tok (B,N,K,D)
    const float* ego  = (const float*)d_in[1];   // ego_ctx (B,N,256)
    const float* r    = (const float*)d_in[2];   // (B,N,K,3)
    const float* u    = (const float*)d_in[3];   // (B,N,K,3)
    const void*  mask = d_in[4];                 // (B,N,K) bool/int
    const float* We   = (const float*)d_in[5];   // W_ego (256,256)
    const float* be   = (const float*)d_in[6];   // b_ego (256)
    const float* lns  = (const float*)d_in[7];   // ln_scale (256)
    const float* lnb  = (const float*)d_in[8];   // ln_bias (256)
    const float* Wh   = (const float*)d_in[9];   // W_h (512,256)
    const float* bh   = (const float*)d_in[10];  // b_h (256)
    const float* Wl   = (const float*)d_in[11];  // W_logit (256,4)
    // d_in[12] = b_logit: softmax-invariant, unused.

    cudaFuncSetAttribute(k_main,   cudaFuncAttributeMaxDynamicSharedMemorySize, MAIN_SMEM);
    cudaFuncSetAttribute(k_egomma, cudaFuncAttributeMaxDynamicSharedMemorySize, EGO_SMEM);

    k_prep<<<272, 256>>>(Wh, We, be, mask);
    k_egomma<<<NTOK/64, 512, EGO_SMEM>>>(ego, bh);
    k_main<<<2048, 1024, MAIN_SMEM>>>(inv, lns, lnb, Wl);
    k_final<<<NTOK/8, 256>>>(r, u, mask, (float*)d_out);
}